// round 14
// baseline (speedup 1.0000x reference)
#include <cuda_runtime.h>
#include <cuda_fp16.h>
#include <math.h>
#include <stdint.h>

// ---------------- problem constants ----------------
#define BATCH   4
#define TSEQ    288
#define TVIS    256
#define TQRY    32
#define DMODEL  1024
#define DINNER  2048
#define NHEADS  32
#define NSTATE  128
#define PDIM    64
#define NLAYERS 12
#define PROJ_DIM 4384
#define EDIM    1536
#define ROWS    (BATCH*TSEQ)    // 1152
#define ALPHA_C 0.5f
#define NBH     (BATCH*NHEADS)  // 128
#define NCH     4
#define CHUNK   72              // 288 = 4 * 72
#define P3TS    18              // 72 = 4 * 18
#define P3TILES (CHUNK/P3TS)    // 4
#define PNSZ    (PDIM*NSTATE)   // 8192

// weight-slice geometry (halves)
#define W_VIS_OFF   0ull
#define W_VIS_PL    (1024ull*1024ull)
#define W_QRY_OFF   (2ull*W_VIS_PL)
#define W_L_OFF     (4ull*W_VIS_PL)
#define W_IN_PL     ((size_t)DMODEL*PROJ_DIM)
#define W_OUT_PL    ((size_t)DINNER*DMODEL)
#define W_L_SZ      (2ull*W_IN_PL + 2ull*W_OUT_PL)
#define W_TOTAL     (W_L_OFF + 2ull*W_L_SZ)

// ---------------- scratch (device globals; no allocation) ----------------
__device__ float g_hidden[ROWS*DMODEL];
__device__ float g_xin   [ROWS*DMODEL];
__device__ float g_proj  [ROWS*PROJ_DIM];
__device__ float g_yraw  [ROWS*DINNER];
__device__ float g_pooled[BATCH*DMODEL];
__device__ float g_vstate[3ull*NBH*PNSZ];   // local states / H_in, 12.6 MB
__device__ float g_cumP  [NBH*TSEQ];
__device__ __align__(16) __half g_ah[2ull*1152*2048];
__device__ __align__(16) __half g_bw[W_TOTAL];

// ---------------- helpers ----------------
__device__ __forceinline__ float block_reduce_sum_256(float v, float* red)
{
    #pragma unroll
    for (int o = 16; o; o >>= 1) v += __shfl_xor_sync(0xffffffffu, v, o);
    const int warp = threadIdx.x >> 5, lane = threadIdx.x & 31;
    if (lane == 0) red[warp] = v;
    __syncthreads();
    if (threadIdx.x < 32) {
        float t = (threadIdx.x < 8) ? red[threadIdx.x] : 0.f;
        #pragma unroll
        for (int o = 4; o; o >>= 1) t += __shfl_xor_sync(0xffffffffu, t, o);
        if (threadIdx.x == 0) red[0] = t;
    }
    __syncthreads();
    return red[0];
}

__device__ __forceinline__ void split2(float x, __half& h0, __half& h1)
{
    h0 = __float2half_rn(x);
    h1 = __float2half_rn(x - __half2float(h0));
}

#define MMA16(cc, aa, bb)                                                        \
  asm volatile("mma.sync.aligned.m16n8k16.row.col.f32.f16.f16.f32 "             \
    "{%0,%1,%2,%3}, {%4,%5,%6,%7}, {%8,%9}, {%0,%1,%2,%3};\n"                    \
    : "+f"((cc)[0]), "+f"((cc)[1]), "+f"((cc)[2]), "+f"((cc)[3])                 \
    : "r"((aa)[0]), "r"((aa)[1]), "r"((aa)[2]), "r"((aa)[3]),                    \
      "r"((bb)[0]), "r"((bb)[1]))

__device__ __forceinline__ void ldsm4(uint32_t* r, uint32_t addr)
{
    asm volatile("ldmatrix.sync.aligned.m8n8.x4.shared.b16 {%0,%1,%2,%3}, [%4];"
                 : "=r"(r[0]), "=r"(r[1]), "=r"(r[2]), "=r"(r[3]) : "r"(addr));
}
__device__ __forceinline__ void ldsm2(uint32_t* r, uint32_t addr)
{
    asm volatile("ldmatrix.sync.aligned.m8n8.x2.shared.b16 {%0,%1}, [%2];"
                 : "=r"(r[0]), "=r"(r[1]) : "r"(addr));
}

__device__ __forceinline__ void cpasync16(uint32_t dst, const void* src, int sz)
{
    asm volatile("cp.async.cg.shared.global [%0], [%1], 16, %2;\n"
                 :: "r"(dst), "l"(src), "r"(sz));
}
__device__ __forceinline__ void cpasync4(uint32_t dst, const void* src)
{
    asm volatile("cp.async.ca.shared.global [%0], [%1], 4;\n"
                 :: "r"(dst), "l"(src));
}

// ---------------- prep: split fp32 -> 2 fp16 planes ----------------
__global__ void split2_x(const float* __restrict__ x, __half* __restrict__ out, size_t S)
{
    size_t i = (size_t)blockIdx.x * blockDim.x + threadIdx.x;
    if (i < S) {
        __half h0, h1; split2(x[i], h0, h1);
        out[i] = h0; out[S + i] = h1;
    }
}

// ---------------- prep: transpose KxN fp32 -> 2 planes [N][K] fp16 ----------------
__global__ void tsplit2f(const float* __restrict__ W, __half* __restrict__ out,
                         int K, int N)
{
    __shared__ float tile[64][33];
    const int n0 = blockIdx.x * 32, k0 = blockIdx.y * 64;
    const int tid = threadIdx.x;
    const int r = tid >> 5, c = tid & 31;
    #pragma unroll
    for (int i = 0; i < 8; i++)
        tile[i*8 + r][c] = W[(size_t)(k0 + i*8 + r) * N + n0 + c];
    __syncthreads();

    const size_t NK = (size_t)N * K;
    const int ns = tid >> 5;
    const int kp = tid & 31;
    #pragma unroll
    for (int j = 0; j < 4; j++) {
        const int nl = j*8 + ns;
        const int n  = n0 + nl;
        const float f0 = tile[2*kp    ][nl];
        const float f1 = tile[2*kp + 1][nl];
        __half a0, a1, b0, b1;
        split2(f0, a0, a1);
        split2(f1, b0, b1);
        __half2* p0 = (__half2*)(out + (size_t)n * K + k0);
        __half2* p1 = (__half2*)(out + NK + (size_t)n * K + k0);
        p0[kp] = __halves2half2(a0, b0);
        p1[kp] = __halves2half2(a1, b1);
    }
}

// ---------------- fp16x2 mma.sync GEMM, BM=64, BN=32*NI, 2 CTAs/SM ----------------
#define APLANE 8192
template<int NI>
__global__ __launch_bounds__(256, 2)
void hgemm_t(const __half* __restrict__ Ah, size_t aplane,
             const __half* __restrict__ Bh, size_t bplane,
             float* __restrict__ C, int M, int N, int K,
             const float* __restrict__ bias, int accum,
             int Tin, int Tout, int toff)
{
    constexpr int BN      = 32 * NI;
    constexpr int BPLANEx = BN * 128;
    constexpr int STAGE   = 2*APLANE + 2*BPLANEx;
    constexpr int TPB     = 256 / BN;

    extern __shared__ char sm[];
    const uint32_t smb = (uint32_t)__cvta_generic_to_shared(sm);

    const int tid  = threadIdx.x;
    const int warp = tid >> 5, lane = tid & 31;
    const int gid  = lane >> 2, tg = lane & 3;
    const int row0 = blockIdx.y * 64;
    const int col0 = blockIdx.x * BN;
    const int m_off = (warp & 1) * 32;
    const int n_off = (warp >> 1) * (8 * NI);

    float c[2][NI][4];
    #pragma unroll
    for (int mi = 0; mi < 2; mi++)
        #pragma unroll
        for (int ni = 0; ni < NI; ni++)
            #pragma unroll
            for (int q = 0; q < 4; q++) c[mi][ni][q] = 0.f;

    const int larow  = tid >> 2;
    const int cbase  = (tid & 3) * 2;
    const int lbrow  = tid / TPB;
    const int cbaseB = (tid % TPB) * NI;
    const int brow   = col0 + lbrow;
    const int bval   = (brow < N) ? 16 : 0;
    const __half* Asrc0 = Ah + (size_t)(row0 + larow) * K;
    const __half* Asrc1 = Asrc0 + aplane;
    const __half* Bsrc0 = Bh + (size_t)((brow < N) ? brow : 0) * K;
    const __half* Bsrc1 = Bsrc0 + bplane;

    const int la   = lane & 15;
    const int asel = lane >> 4;
    const int lb   = lane & 7;
    const int bsel = (lane >> 3) & 1;
    uint32_t aoff[2]; int ar7[2];
    #pragma unroll
    for (int mi = 0; mi < 2; mi++) {
        const int r = m_off + mi*16 + la;
        aoff[mi] = (uint32_t)r * 128;
        ar7[mi]  = r & 7;
    }
    uint32_t boff[NI]; int br7[NI];
    #pragma unroll
    for (int ni = 0; ni < NI; ni++) {
        const int r = n_off + ni*8 + lb;
        boff[ni] = (uint32_t)r * 128;
        br7[ni]  = r & 7;
    }

    const int nc = K >> 6;

    {
        const uint32_t sb = smb;
        #pragma unroll
        for (int j = 0; j < 2; j++) {
            const int ch = cbase + j;
            const uint32_t sw = (uint32_t)((ch ^ (larow & 7)) << 4);
            cpasync16(sb + larow*128 + sw,          Asrc0 + ch*8, 16);
            cpasync16(sb + APLANE + larow*128 + sw, Asrc1 + ch*8, 16);
        }
        #pragma unroll
        for (int j = 0; j < NI; j++) {
            const int ch = cbaseB + j;
            const uint32_t sw = (uint32_t)((ch ^ (lbrow & 7)) << 4);
            cpasync16(sb + 2*APLANE + lbrow*128 + sw,           Bsrc0 + ch*8, bval);
            cpasync16(sb + 2*APLANE + BPLANEx + lbrow*128 + sw, Bsrc1 + ch*8, bval);
        }
        asm volatile("cp.async.commit_group;\n");
    }

    for (int kc = 0; kc < nc; kc++) {
        if (kc + 1 < nc) {
            const int k0 = (kc + 1) << 6;
            const uint32_t sb = smb + ((kc + 1) & 1) * STAGE;
            #pragma unroll
            for (int j = 0; j < 2; j++) {
                const int ch = cbase + j;
                const uint32_t sw = (uint32_t)((ch ^ (larow & 7)) << 4);
                cpasync16(sb + larow*128 + sw,          Asrc0 + k0 + ch*8, 16);
                cpasync16(sb + APLANE + larow*128 + sw, Asrc1 + k0 + ch*8, 16);
            }
            #pragma unroll
            for (int j = 0; j < NI; j++) {
                const int ch = cbaseB + j;
                const uint32_t sw = (uint32_t)((ch ^ (lbrow & 7)) << 4);
                cpasync16(sb + 2*APLANE + lbrow*128 + sw,           Bsrc0 + k0 + ch*8, bval);
                cpasync16(sb + 2*APLANE + BPLANEx + lbrow*128 + sw, Bsrc1 + k0 + ch*8, bval);
            }
        }
        asm volatile("cp.async.commit_group;\n");
        asm volatile("cp.async.wait_group 1;\n");
        __syncthreads();

        const uint32_t S0 = smb + (kc & 1) * STAGE;
        const uint32_t S1 = S0 + APLANE;
        const uint32_t S2 = S0 + 2*APLANE;
        const uint32_t S3 = S2 + BPLANEx;

        #pragma unroll
        for (int s = 0; s < 4; s++) {
            uint32_t b0[NI][2], b1[NI][2];
            #pragma unroll
            for (int ni = 0; ni < NI; ni++) {
                const uint32_t swb = (uint32_t)(((2*s + bsel) ^ br7[ni]) << 4);
                ldsm2(b0[ni], S2 + boff[ni] + swb);
                ldsm2(b1[ni], S3 + boff[ni] + swb);
            }
            #pragma unroll
            for (int mi = 0; mi < 2; mi++) {
                const uint32_t swa = (uint32_t)(((2*s + asel) ^ ar7[mi]) << 4);
                uint32_t a0[4], a1[4];
                ldsm4(a0, S0 + aoff[mi] + swa);
                ldsm4(a1, S1 + aoff[mi] + swa);
                #pragma unroll
                for (int ni = 0; ni < NI; ni++) {
                    MMA16(c[mi][ni], a0, b0[ni]);
                    MMA16(c[mi][ni], a0, b1[ni]);
                    MMA16(c[mi][ni], a1, b0[ni]);
                }
            }
        }
        __syncthreads();
    }

    #pragma unroll
    for (int mi = 0; mi < 2; mi++) {
        #pragma unroll
        for (int half = 0; half < 2; half++) {
            const int r = row0 + m_off + mi*16 + gid + half*8;
            const int orow = (r / Tin) * Tout + toff + (r % Tin);
            #pragma unroll
            for (int ni = 0; ni < NI; ni++) {
                const int col = col0 + n_off + ni*8 + tg*2;
                if (col < N) {
                    float v0 = c[mi][ni][half*2 + 0];
                    float v1 = c[mi][ni][half*2 + 1];
                    if (bias) { v0 += bias[col]; v1 += bias[col+1]; }
                    float* dst = C + (size_t)orow * N + col;
                    if (accum) { v0 += dst[0]; v1 += dst[1]; }
                    *reinterpret_cast<float2*>(dst) = make_float2(v0, v1);
                }
            }
        }
    }
}

#define GSMEM4 (2*(2*APLANE + 2*128*128))
#define GSMEM2 (2*(2*APLANE + 2*64*128))

// ---------------- RMSNorm (fp32 out, final layer) ----------------
__global__ void rmsnorm_k(const float* __restrict__ x, const float* __restrict__ w,
                          float* __restrict__ out, int D)
{
    __shared__ float red[32];
    const int r = blockIdx.x;
    const float* xr = x + (size_t)r * D;
    float s = 0.f;
    for (int d = threadIdx.x; d < D; d += 256) { float v = xr[d]; s = fmaf(v, v, s); }
    const float tot = block_reduce_sum_256(s, red);
    const float rms = rsqrtf(tot / (float)D + 1e-5f);
    for (int d = threadIdx.x; d < D; d += 256)
        out[(size_t)r * D + d] = xr[d] * rms * w[d];
}

// ---------------- RMSNorm fused with fp16x2 split (D = 1024) ----------------
__global__ void rmsnorm_split_k(const float* __restrict__ x, const float* __restrict__ w,
                                __half* __restrict__ out, size_t S)
{
    __shared__ float red[32];
    const int r = blockIdx.x;
    const int tid = threadIdx.x;
    const float4 xv = *(const float4*)(x + (size_t)r * DMODEL + tid*4);
    const float4 wv = *(const float4*)(w + tid*4);
    float s = xv.x*xv.x + xv.y*xv.y + xv.z*xv.z + xv.w*xv.w;
    const float tot = block_reduce_sum_256(s, red);
    const float rms = rsqrtf(tot / (float)DMODEL + 1e-5f);
    float v0 = xv.x*rms*wv.x, v1 = xv.y*rms*wv.y, v2 = xv.z*rms*wv.z, v3 = xv.w*rms*wv.w;
    __half h0a, h1a, h0b, h1b, h0c, h1c, h0d, h1d;
    split2(v0, h0a, h1a); split2(v1, h0b, h1b);
    split2(v2, h0c, h1c); split2(v3, h0d, h1d);
    __half2* p0 = (__half2*)(out + (size_t)r * DMODEL);
    __half2* p1 = (__half2*)(out + S + (size_t)r * DMODEL);
    p0[tid*2]   = __halves2half2(h0a, h0b);
    p0[tid*2+1] = __halves2half2(h0c, h0d);
    p1[tid*2]   = __halves2half2(h1a, h1b);
    p1[tid*2+1] = __halves2half2(h1c, h1d);
}

// ---------------- scan phase 1: NCH local scans ----------------
#define SCX  0
#define SCB  64
#define SCC  192
#define SCDT 320
__global__ void scan_p1(const float* __restrict__ proj,
                        const float* __restrict__ dt_bias,
                        const float* __restrict__ A_log,
                        const float* __restrict__ Dssm,
                        float* __restrict__ yraw,
                        float* __restrict__ vstate,
                        float* __restrict__ cumP)
{
    const int bh   = blockIdx.x;
    const int ch   = blockIdx.y;            // 0..NCH-1
    const int b    = bh >> 5;
    const int h    = bh & 31;
    const int t0   = ch * CHUNK;
    const int t1   = t0 + CHUNK;
    const int tid  = threadIdx.x;
    const int warp = tid >> 5, lane = tid & 31;

    __shared__ float st[3][324];

    const float dtb  = dt_bias[h];
    const float Aval = -expf(A_log[h]);
    const float Dval = Dssm[h];

    float hs[8][4];
    #pragma unroll
    for (int i = 0; i < 8; i++)
        #pragma unroll
        for (int j = 0; j < 4; j++) hs[i][j] = 0.f;

    const int pbase = warp * 8;
    const int nbase = lane * 4;
    const bool s4 = (lane & 16) != 0;
    const bool s3 = (lane & 8)  != 0;
    const bool s2v = (lane & 4) != 0;
    const int  sidx = (lane >> 2) & 7;
    const bool swr  = ((lane & 3) == 0);

    float xprev[8], bprev[4], dtprev = 0.f;
    #pragma unroll
    for (int i = 0; i < 8; i++) xprev[i] = 0.f;
    #pragma unroll
    for (int j = 0; j < 4; j++) bprev[j] = 0.f;
    if (ch > 0) {
        const float* pp = proj + (size_t)(b * TSEQ + t0 - 1) * PROJ_DIM;
        #pragma unroll
        for (int i = 0; i < 8; i++) xprev[i] = pp[DINNER + h*PDIM + pbase + i];
        #pragma unroll
        for (int j = 0; j < 4; j++) bprev[j] = pp[2*DINNER + nbase + j];
        const float v = pp[2*DINNER + 2*NSTATE + h] + dtb;
        dtprev = (v > 20.f) ? v : log1pf(expf(v));
    }

    uint32_t stb[3];
    stb[0] = (uint32_t)__cvta_generic_to_shared(&st[0][0]);
    stb[1] = (uint32_t)__cvta_generic_to_shared(&st[1][0]);
    stb[2] = (uint32_t)__cvta_generic_to_shared(&st[2][0]);

    auto issue = [&](int buf, int t) {
        const float* pr = proj + (size_t)(b * TSEQ + t) * PROJ_DIM;
        const uint32_t base = stb[buf];
        if (tid < 16)
            cpasync16(base + (SCX + tid*4)*4,  pr + DINNER + h*PDIM + tid*4, 16);
        else if (tid < 48)
            cpasync16(base + (SCB + (tid-16)*4)*4, pr + 2*DINNER + (tid-16)*4, 16);
        else if (tid < 80)
            cpasync16(base + (SCC + (tid-48)*4)*4, pr + 2*DINNER + NSTATE + (tid-48)*4, 16);
        else if (tid == 80)
            cpasync4(base + SCDT*4, pr + 2*DINNER + 2*NSTATE + h);
        asm volatile("cp.async.commit_group;\n");
    };

    issue(0, t0);
    issue(1, t0 + 1);

    float cum = 1.f;
    int buf = 0;
    for (int t = t0; t < t1; t++) {
        asm volatile("cp.async.wait_group 1;\n");
        __syncthreads();
        if (t + 2 < t1) {
            int nb = buf + 2; if (nb >= 3) nb -= 3;
            issue(nb, t + 2);
        } else {
            asm volatile("cp.async.commit_group;\n");
        }

        const float* sb = st[buf];
        const float vdt = sb[SCDT] + dtb;
        const float dt  = (vdt > 20.f) ? vdt : log1pf(expf(vdt));
        const float da  = expf(dt * Aval);
        const float cu  = (1.f - ALPHA_C) * dt;
        const float cup = da * ALPHA_C * dtprev;
        if (ch > 0) {
            cum *= da;
            if (tid == 0) cumP[bh * TSEQ + t] = cum;
        }

        float bc[4], cc[4];
        #pragma unroll
        for (int j = 0; j < 4; j++) { bc[j] = sb[SCB + nbase + j]; cc[j] = sb[SCC + nbase + j]; }

        const int row = b * TSEQ + t;

        float v[8];
        #pragma unroll
        for (int i = 0; i < 8; i++) {
            const float xr  = sb[SCX + pbase + i];
            const float xpi = cup * xprev[i];
            const float xci = cu  * xr;
            float yp = 0.f;
            #pragma unroll
            for (int j = 0; j < 4; j++) {
                const float u = fmaf(xpi, bprev[j], xci * bc[j]);
                hs[i][j] = fmaf(da, hs[i][j], u);
                yp = fmaf(hs[i][j], cc[j], yp);
            }
            v[i] = yp;
            xprev[i] = xr;
        }

        float w4[4];
        #pragma unroll
        for (int i = 0; i < 4; i++) {
            const float send = s4 ? v[i]   : v[i+4];
            const float keep = s4 ? v[i+4] : v[i];
            w4[i] = keep + __shfl_xor_sync(0xffffffffu, send, 16);
        }
        float x2[2];
        #pragma unroll
        for (int i = 0; i < 2; i++) {
            const float send = s3 ? w4[i]   : w4[i+2];
            const float keep = s3 ? w4[i+2] : w4[i];
            x2[i] = keep + __shfl_xor_sync(0xffffffffu, send, 8);
        }
        float y;
        {
            const float send = s2v ? x2[0] : x2[1];
            const float keep = s2v ? x2[1] : x2[0];
            y = keep + __shfl_xor_sync(0xffffffffu, send, 4);
        }
        y += __shfl_xor_sync(0xffffffffu, y, 2);
        y += __shfl_xor_sync(0xffffffffu, y, 1);

        if (swr)
            yraw[(size_t)row * DINNER + h*PDIM + pbase + sidx] =
                fmaf(Dval, sb[SCX + pbase + sidx], y);

        #pragma unroll
        for (int j = 0; j < 4; j++) bprev[j] = bc[j];
        dtprev = dt;
        buf++; if (buf >= 3) buf = 0;
    }

    // chunks 0..NCH-2: store final local state in slice ch
    if (ch < NCH - 1) {
        float* V = vstate + ((size_t)ch * NBH + bh) * PNSZ;
        #pragma unroll
        for (int i = 0; i < 8; i++)
            #pragma unroll
            for (int j = 0; j < 4; j++)
                V[(pbase + i) * NSTATE + nbase + j] = hs[i][j];
    }
}

// ---------------- scan phase 2: prefix combine (slice c-1 -> H_in(c)) ----------
__global__ void scan_p2(float* __restrict__ vstate, const float* __restrict__ cumP)
{
    const int bh  = blockIdx.x;
    const int tid = threadIdx.x;
    const float Pe1 = cumP[bh * TSEQ + 1*CHUNK + CHUNK - 1];
    const float Pe2 = cumP[bh * TSEQ + 2*CHUNK + CHUNK - 1];
    float* V0 = vstate + ((size_t)0 * NBH + bh) * PNSZ;
    float* V1 = vstate + ((size_t)1 * NBH + bh) * PNSZ;
    float* V2 = vstate + ((size_t)2 * NBH + bh) * PNSZ;
    #pragma unroll
    for (int e = 0; e < PNSZ/256; e++) {
        const int idx = tid + e * 256;
        const float f0 = V0[idx];                   // H_in(1) — stays in place
        const float f1 = fmaf(Pe1, f0, V1[idx]);    // H_in(2)
        V1[idx] = f1;
        const float f2 = fmaf(Pe2, f1, V2[idx]);    // H_in(3)
        V2[idx] = f2;
    }
}

// ---------------- scan phase 3: y_t += P_t * (C_t . H_in(c)), chunks 1..3 --------
__global__ void scan_p3(const float* __restrict__ proj,
                        const float* __restrict__ vstate,
                        const float* __restrict__ cumP,
                        float* __restrict__ yraw)
{
    const int bh   = blockIdx.x;
    const int ch   = 1 + (int)blockIdx.y / P3TILES;
    const int tile = (int)blockIdx.y % P3TILES;
    const int b    = bh >> 5;
    const int h    = bh & 31;
    const int tid  = threadIdx.x;
    const int warp = tid >> 5, lane = tid & 31;
    const int pbase = warp * 8;
    const int nbase = lane * 4;
    const bool s4 = (lane & 16) != 0;
    const bool s3 = (lane & 8)  != 0;
    const bool s2v = (lane & 4) != 0;
    const int  sidx = (lane >> 2) & 7;
    const bool swr  = ((lane & 3) == 0);

    const float* V = vstate + ((size_t)(ch - 1) * NBH + bh) * PNSZ;
    float hin[8][4];
    #pragma unroll
    for (int i = 0; i < 8; i++) {
        const float4 q = *(const float4*)(V + (pbase + i) * NSTATE + nbase);
        hin[i][0] = q.x; hin[i][1] = q.y; hin[i][2] = q.z; hin[i][3] = q.w;
    }

    const int t0 = ch * CHUNK + tile * P3TS;
    for (int t = t0; t < t0 + P3TS; t++) {
        const int row = b * TSEQ + t;
        const float* pr = proj + (size_t)row * PROJ_DIM;
        const float Pt = cumP[bh * TSEQ + t];

        const float4 cq = *(const float4*)(pr + 2*DINNER + NSTATE + nbase);
        float cc[4] = {cq.x, cq.y, cq.z, cq.w};

        float v[8];
        #pragma unroll
        for (int i = 0; i < 8; i++) {
            float yp = 0.f;
            #pragma unroll
            for (int j = 0; j < 4; j++) yp = fmaf(hin[i][j], cc[j], yp);
            v[i] = yp;
        }

        float w4[4];
        #pragma unroll
        for (int i = 0; i < 4; i++) {
            const float send = s4 ? v[i]   : v[i+4];
            const float keep = s4 ? v[i+4] : v[i];
            w4[i] = keep + __shfl_xor_sync(0xffffffffu, send, 16);
        }
        float x2[2];
        #pragma unroll
        for (int i = 0; i < 2; i++) {
            const float send = s3 ? w4[i]   : w4[i+2];
            const float keep = s3 ? w4[i+2] : w4[i];
            x2[i] = keep + __shfl_xor_sync(0xffffffffu, send, 8);
        }
        float y;
        {
            const float send = s2v ? x2[0] : x2[1];
            const float keep = s2v ? x2[1] : x2[0];
            y = keep + __shfl_xor_sync(0xffffffffu, send, 4);
        }
        y += __shfl_xor_sync(0xffffffffu, y, 2);
        y += __shfl_xor_sync(0xffffffffu, y, 1);

        if (swr) {
            float* dst = yraw + (size_t)row * DINNER + h*PDIM + pbase + sidx;
            *dst = fmaf(Pt, y, *dst);
        }
    }
}

// ---------------- gate + gnorm fused with fp16x2 split (register-resident) --------
__global__ void gate_gnorm_split_k(const float* __restrict__ proj,
                                   const float* __restrict__ yraw,
                                   const float* __restrict__ gw,
                                   __half* __restrict__ out, size_t S)
{
    __shared__ float red[32];
    const int r = blockIdx.x;
    const int tid = threadIdx.x;
    const float* pz = proj + (size_t)r * PROJ_DIM;
    const float* yr = yraw + (size_t)r * DINNER;

    float g[2][4];
    float s = 0.f;
    #pragma unroll
    for (int it = 0; it < 2; it++) {
        const int d = (tid + it*256) * 4;
        const float4 zv = *(const float4*)(pz + d);
        const float4 yv = *(const float4*)(yr + d);
        g[it][0] = yv.x * zv.x / (1.f + expf(-zv.x));
        g[it][1] = yv.y * zv.y / (1.f + expf(-zv.y));
        g[it][2] = yv.z * zv.z / (1.f + expf(-zv.z));
        g[it][3] = yv.w * zv.w / (1.f + expf(-zv.w));
        s += g[it][0]*g[it][0] + g[it][1]*g[it][1] + g[it][2]*g[it][2] + g[it][3]*g[it][3];
    }
    const float tot = block_reduce_sum_256(s, red);
    const float rms = rsqrtf(tot / (float)DINNER + 1e-5f);

    __half2* p0 = (__half2*)(out + (size_t)r * DINNER);
    __half2* p1 = (__half2*)(out + S + (size_t)r * DINNER);
    #pragma unroll
    for (int it = 0; it < 2; it++) {
        const int d = (tid + it*256) * 4;
        const float4 wv = *(const float4*)(gw + d);
        float v0 = g[it][0]*rms*wv.x, v1 = g[it][1]*rms*wv.y;
        float v2 = g[it][2]*rms*wv.z, v3 = g[it][3]*rms*wv.w;
        __half h0a, h1a, h0b, h1b, h0c, h1c, h0d, h1d;
        split2(v0, h0a, h1a); split2(v1, h0b, h1b);
        split2(v2, h0c, h1c); split2(v3, h0d, h1d);
        p0[d/2]   = __halves2half2(h0a, h0b);
        p0[d/2+1] = __halves2half2(h0c, h0d);
        p1[d/2]   = __halves2half2(h1a, h1b);
        p1[d/2+1] = __halves2half2(h1c, h1d);
    }
}

// ---------------- mean over T per batch ----------------
__global__ void pool_k(const float* __restrict__ xin, float* __restrict__ pooled)
{
    const int b = blockIdx.x;
    const int d = blockIdx.y * 256 + threadIdx.x;
    float s = 0.f;
    for (int t = 0; t < TSEQ; t++)
        s += xin[(size_t)(b*TSEQ + t) * DMODEL + d];
    pooled[b*DMODEL + d] = s * (1.f / (float)TSEQ);
}

// ---------------- head GEMM + bias + L2-normalize ----------------
__global__ void head_k(const float* __restrict__ pooled,
                       const float* __restrict__ hw,
                       const float* __restrict__ hb,
                       float* __restrict__ out)
{
    __shared__ float sp[DMODEL];
    __shared__ float so[EDIM];
    __shared__ float red[32];
    const int b = blockIdx.x;

    for (int d = threadIdx.x; d < DMODEL; d += 256) sp[d] = pooled[b*DMODEL + d];
    __syncthreads();

    float acc[EDIM/256];
    #pragma unroll
    for (int m = 0; m < EDIM/256; m++) acc[m] = hb[threadIdx.x + m*256];
    for (int k = 0; k < DMODEL; k++) {
        const float p = sp[k];
        #pragma unroll
        for (int m = 0; m < EDIM/256; m++)
            acc[m] = fmaf(p, hw[(size_t)k*EDIM + threadIdx.x + m*256], acc[m]);
    }
    #pragma unroll
    for (int m = 0; m < EDIM/256; m++) so[threadIdx.x + m*256] = acc[m];
    __syncthreads();

    float s = 0.f;
    for (int e = threadIdx.x; e < EDIM; e += 256) s = fmaf(so[e], so[e], s);
    const float tot = block_reduce_sum_256(s, red);
    const float inv = 1.f / fmaxf(sqrtf(tot), 1e-12f);
    for (int e = threadIdx.x; e < EDIM; e += 256)
        out[(size_t)b*EDIM + e] = so[e] * inv;
}

// ---------------- host launcher ----------------
extern "C" void kernel_launch(void* const* d_in, const int* in_sizes, int n_in,
                              void* d_out, int out_size)
{
    const float* visual   = (const float*)d_in[0];
    const float* query    = (const float*)d_in[1];
    const float* vis_w    = (const float*)d_in[2];
    const float* vis_b    = (const float*)d_in[3];
    const float* qry_w    = (const float*)d_in[4];
    const float* qry_b    = (const float*)d_in[5];
    const float* norm_ws  = (const float*)d_in[6];
    const float* in_ws    = (const float*)d_in[7];
    const float* dt_bias  = (const float*)d_in[8];
    const float* A_logs   = (const float*)d_in[9];
    const float* D_ssm    = (const float*)d_in[10];
    const float* gnorm_ws = (const float*)d_in[11];
    const float* out_ws   = (const float*)d_in[12];
    const float* norm_f_w = (const float*)d_in[13];
    const float* head_w   = (const float*)d_in[14];
    const float* head_b   = (const float*)d_in[15];
    float* out = (float*)d_out;

    float *hidden, *xin, *proj, *yraw, *pooled, *vstate, *cumP;
    __half *ah, *bw;
    cudaGetSymbolAddress((void**)&hidden, g_hidden);
    cudaGetSymbolAddress((void**)&xin,    g_xin);
    cudaGetSymbolAddress((void**)&proj,   g_proj);
    cudaGetSymbolAddress((void**)&yraw,   g_yraw);
    cudaGetSymbolAddress((void**)&pooled, g_pooled);
    cudaGetSymbolAddress((void**)&vstate, g_vstate);
    cudaGetSymbolAddress((void**)&cumP,   g_cumP);
    cudaGetSymbolAddress((void**)&ah,     g_ah);
    cudaGetSymbolAddress((void**)&bw,     g_bw);

    cudaFuncSetAttribute(hgemm_t<4>, cudaFuncAttributeMaxDynamicSharedMemorySize, GSMEM4);
    cudaFuncSetAttribute(hgemm_t<2>, cudaFuncAttributeMaxDynamicSharedMemorySize, GSMEM2);

    const dim3 blk(256);

    cudaStream_t s2;
    cudaStreamCreateWithFlags(&s2, cudaStreamNonBlocking);
    cudaEvent_t evFork, evS[NLAYERS], evP[NLAYERS];
    cudaEventCreateWithFlags(&evFork, cudaEventDisableTiming);
    for (int i = 0; i < NLAYERS; i++) {
        cudaEventCreateWithFlags(&evS[i], cudaEventDisableTiming);
        cudaEventCreateWithFlags(&evP[i], cudaEventDisableTiming);
    }

    auto slice = [&](int i) -> __half* { return bw + W_L_OFF + (size_t)(i & 1) * W_L_SZ; };

    cudaEventRecord(evFork, 0);
    cudaStreamWaitEvent(s2, evFork, 0);
    tsplit2f<<<dim3(PROJ_DIM/32, DMODEL/64), blk, 0, s2>>>(in_ws, slice(0), DMODEL, PROJ_DIM);
    tsplit2f<<<dim3(DMODEL/32, DINNER/64), blk, 0, s2>>>(out_ws, slice(0) + 2*W_IN_PL, DINNER, DMODEL);
    cudaEventRecord(evP[0], s2);

    // ---- initial projections into hidden[b, t, :] ----
    {
        const size_t S = (size_t)BATCH*TVIS*DMODEL;
        split2_x<<<(unsigned)((S + 255)/256), blk>>>(visual, ah, S);
        tsplit2f<<<dim3(DMODEL/32, DMODEL/64), blk>>>(vis_w, bw + W_VIS_OFF, DMODEL, DMODEL);
        hgemm_t<2><<<dim3(DMODEL/64, (BATCH*TVIS)/64), blk, GSMEM2>>>(
            ah, S, bw + W_VIS_OFF, W_VIS_PL, hidden,
            BATCH*TVIS, DMODEL, DMODEL, vis_b, 0, TVIS, TSEQ, 0);
    }
    {
        const size_t S = (size_t)BATCH*TQRY*DMODEL;
        split2_x<<<(unsigned)((S + 255)/256), blk>>>(query, ah, S);
        tsplit2f<<<dim3(DMODEL/32, DMODEL/64), blk>>>(qry_w, bw + W_QRY_OFF, DMODEL, DMODEL);
        hgemm_t<2><<<dim3(DMODEL/64, (BATCH*TQRY)/64), blk, GSMEM2>>>(
            ah, S, bw + W_QRY_OFF, W_VIS_PL, hidden,
            BATCH*TQRY, DMODEL, DMODEL, qry_b, 0, TQRY, TSEQ, TVIS);
    }

    for (int i = 0; i < NLAYERS; i++) {
        const size_t SA = (size_t)ROWS*DMODEL;
        rmsnorm_split_k<<<ROWS, blk>>>(hidden, norm_ws + (size_t)i*DMODEL, ah, SA);

        cudaStreamWaitEvent(0, evP[i], 0);
        hgemm_t<4><<<dim3((PROJ_DIM + 127)/128, ROWS/64), blk, GSMEM4>>>(
            ah, SA, slice(i), W_IN_PL, proj,
            ROWS, PROJ_DIM, DMODEL, nullptr, 0, ROWS, ROWS, 0);

        // 4-chunk scan: parallel local scans, prefix combine, parallel correction
        scan_p1<<<dim3(NBH, NCH), blk>>>(
            proj, dt_bias + (size_t)i*NHEADS, A_logs + (size_t)i*NHEADS,
            D_ssm + (size_t)i*NHEADS, yraw, vstate, cumP);
        cudaEventRecord(evS[i], 0);

        if (i + 1 < NLAYERS) {
            cudaStreamWaitEvent(s2, evS[i], 0);
            tsplit2f<<<dim3(PROJ_DIM/32, DMODEL/64), blk, 0, s2>>>(
                in_ws + (size_t)(i+1)*DMODEL*PROJ_DIM, slice(i+1), DMODEL, PROJ_DIM);
            tsplit2f<<<dim3(DMODEL/32, DINNER/64), blk, 0, s2>>>(
                out_ws + (size_t)(i+1)*DINNER*DMODEL, slice(i+1) + 2*W_IN_PL, DINNER, DMODEL);
            cudaEventRecord(evP[i+1], s2);
        }

        scan_p2<<<NBH, blk>>>(vstate, cumP);
        scan_p3<<<dim3(NBH, (NCH-1)*P3TILES), blk>>>(proj, vstate, cumP, yraw);

        const size_t SG = (size_t)ROWS*DINNER;
        gate_gnorm_split_k<<<ROWS, blk>>>(proj, yraw, gnorm_ws + (size_t)i*DINNER, ah, SG);

        hgemm_t<2><<<dim3(DMODEL/64, ROWS/64), blk, GSMEM2>>>(
            ah, SG, slice(i) + 2*W_IN_PL, W_OUT_PL, hidden,
            ROWS, DMODEL, DINNER, nullptr, 1, ROWS, ROWS, 0);
    }

    rmsnorm_k<<<ROWS, blk>>>(hidden, norm_f_w, xin, DMODEL);
    pool_k<<<dim3(BATCH, DMODEL/256), blk>>>(xin, pooled);
    head_k<<<BATCH, blk>>>(pooled, head_w, head_b, out);
}

// round 15
// speedup vs baseline: 1.1162x; 1.1162x over previous
#include <cuda_runtime.h>
#include <cuda_fp16.h>
#include <math.h>
#include <stdint.h>

// ---------------- problem constants ----------------
#define BATCH   4
#define TSEQ    288
#define TVIS    256
#define TQRY    32
#define DMODEL  1024
#define DINNER  2048
#define NHEADS  32
#define NSTATE  128
#define PDIM    64
#define NLAYERS 12
#define PROJ_DIM 4384
#define EDIM    1536
#define ROWS    (BATCH*TSEQ)    // 1152
#define ALPHA_C 0.5f
#define NBH     (BATCH*NHEADS)  // 128
#define CHUNK   144             // 2 chunks of 144
#define P3TS    16              // 144 = 9*16
#define PNSZ    (PDIM*NSTATE)

// weight-slice geometry (halves)
#define W_VIS_OFF   0ull
#define W_VIS_PL    (1024ull*1024ull)
#define W_QRY_OFF   (2ull*W_VIS_PL)
#define W_L_OFF     (4ull*W_VIS_PL)
#define W_IN_PL     ((size_t)DMODEL*PROJ_DIM)
#define W_OUT_PL    ((size_t)DINNER*DMODEL)
#define W_L_SZ      (2ull*W_IN_PL + 2ull*W_OUT_PL)
#define W_TOTAL     (W_L_OFF + 2ull*W_L_SZ)

// ---------------- scratch (device globals; no allocation) ----------------
__device__ float g_hidden[ROWS*DMODEL];
__device__ float g_xin   [ROWS*DMODEL];
__device__ float g_proj  [ROWS*PROJ_DIM];
__device__ float g_yraw  [ROWS*DINNER];
__device__ float g_pooled[BATCH*DMODEL];
__device__ float g_vstate[(size_t)NBH*PNSZ];
__device__ float g_cumP  [NBH*TSEQ];
__device__ float g_dt    [NBH*TSEQ];
__device__ float g_da    [NBH*TSEQ];
__device__ __align__(16) __half g_ah[2ull*1152*2048];
__device__ __align__(16) __half g_bw[W_TOTAL];

// ---------------- helpers ----------------
__device__ __forceinline__ float block_reduce_sum_256(float v, float* red)
{
    #pragma unroll
    for (int o = 16; o; o >>= 1) v += __shfl_xor_sync(0xffffffffu, v, o);
    const int warp = threadIdx.x >> 5, lane = threadIdx.x & 31;
    if (lane == 0) red[warp] = v;
    __syncthreads();
    if (threadIdx.x < 32) {
        float t = (threadIdx.x < 8) ? red[threadIdx.x] : 0.f;
        #pragma unroll
        for (int o = 4; o; o >>= 1) t += __shfl_xor_sync(0xffffffffu, t, o);
        if (threadIdx.x == 0) red[0] = t;
    }
    __syncthreads();
    return red[0];
}

__device__ __forceinline__ void split2(float x, __half& h0, __half& h1)
{
    h0 = __float2half_rn(x);
    h1 = __float2half_rn(x - __half2float(h0));
}

#define MMA16(cc, aa, bb)                                                        \
  asm volatile("mma.sync.aligned.m16n8k16.row.col.f32.f16.f16.f32 "             \
    "{%0,%1,%2,%3}, {%4,%5,%6,%7}, {%8,%9}, {%0,%1,%2,%3};\n"                    \
    : "+f"((cc)[0]), "+f"((cc)[1]), "+f"((cc)[2]), "+f"((cc)[3])                 \
    : "r"((aa)[0]), "r"((aa)[1]), "r"((aa)[2]), "r"((aa)[3]),                    \
      "r"((bb)[0]), "r"((bb)[1]))

__device__ __forceinline__ void ldsm4(uint32_t* r, uint32_t addr)
{
    asm volatile("ldmatrix.sync.aligned.m8n8.x4.shared.b16 {%0,%1,%2,%3}, [%4];"
                 : "=r"(r[0]), "=r"(r[1]), "=r"(r[2]), "=r"(r[3]) : "r"(addr));
}
__device__ __forceinline__ void ldsm2(uint32_t* r, uint32_t addr)
{
    asm volatile("ldmatrix.sync.aligned.m8n8.x2.shared.b16 {%0,%1}, [%2];"
                 : "=r"(r[0]), "=r"(r[1]) : "r"(addr));
}

__device__ __forceinline__ void cpasync16(uint32_t dst, const void* src, int sz)
{
    asm volatile("cp.async.cg.shared.global [%0], [%1], 16, %2;\n"
                 :: "r"(dst), "l"(src), "r"(sz));
}
__device__ __forceinline__ void cpasync4(uint32_t dst, const void* src)
{
    asm volatile("cp.async.ca.shared.global [%0], [%1], 4;\n"
                 :: "r"(dst), "l"(src));
}

// ---------------- prep: split fp32 -> 2 fp16 planes ----------------
__global__ void split2_x(const float* __restrict__ x, __half* __restrict__ out, size_t S)
{
    size_t i = (size_t)blockIdx.x * blockDim.x + threadIdx.x;
    if (i < S) {
        __half h0, h1; split2(x[i], h0, h1);
        out[i] = h0; out[S + i] = h1;
    }
}

// ---------------- prep: transpose KxN fp32 -> 2 planes [N][K] fp16 ----------------
__global__ void tsplit2f(const float* __restrict__ W, __half* __restrict__ out,
                         int K, int N)
{
    __shared__ float tile[64][33];
    const int n0 = blockIdx.x * 32, k0 = blockIdx.y * 64;
    const int tid = threadIdx.x;
    const int r = tid >> 5, c = tid & 31;
    #pragma unroll
    for (int i = 0; i < 8; i++)
        tile[i*8 + r][c] = W[(size_t)(k0 + i*8 + r) * N + n0 + c];
    __syncthreads();

    const size_t NK = (size_t)N * K;
    const int ns = tid >> 5;
    const int kp = tid & 31;
    #pragma unroll
    for (int j = 0; j < 4; j++) {
        const int nl = j*8 + ns;
        const int n  = n0 + nl;
        const float f0 = tile[2*kp    ][nl];
        const float f1 = tile[2*kp + 1][nl];
        __half a0, a1, b0, b1;
        split2(f0, a0, a1);
        split2(f1, b0, b1);
        __half2* p0 = (__half2*)(out + (size_t)n * K + k0);
        __half2* p1 = (__half2*)(out + NK + (size_t)n * K + k0);
        p0[kp] = __halves2half2(a0, b0);
        p1[kp] = __halves2half2(a1, b1);
    }
}

// ---------------- fp16x2 mma.sync GEMM, BM=64, BN=32*NI, 2 CTAs/SM ----------------
#define APLANE 8192
template<int NI>
__global__ __launch_bounds__(256, 2)
void hgemm_t(const __half* __restrict__ Ah, size_t aplane,
             const __half* __restrict__ Bh, size_t bplane,
             float* __restrict__ C, int M, int N, int K,
             const float* __restrict__ bias, int accum,
             int Tin, int Tout, int toff)
{
    constexpr int BN      = 32 * NI;
    constexpr int BPLANEx = BN * 128;
    constexpr int STAGE   = 2*APLANE + 2*BPLANEx;
    constexpr int TPB     = 256 / BN;

    extern __shared__ char sm[];
    const uint32_t smb = (uint32_t)__cvta_generic_to_shared(sm);

    const int tid  = threadIdx.x;
    const int warp = tid >> 5, lane = tid & 31;
    const int gid  = lane >> 2, tg = lane & 3;
    const int row0 = blockIdx.y * 64;
    const int col0 = blockIdx.x * BN;
    const int m_off = (warp & 1) * 32;
    const int n_off = (warp >> 1) * (8 * NI);

    float c[2][NI][4];
    #pragma unroll
    for (int mi = 0; mi < 2; mi++)
        #pragma unroll
        for (int ni = 0; ni < NI; ni++)
            #pragma unroll
            for (int q = 0; q < 4; q++) c[mi][ni][q] = 0.f;

    const int larow  = tid >> 2;
    const int cbase  = (tid & 3) * 2;
    const int lbrow  = tid / TPB;
    const int cbaseB = (tid % TPB) * NI;
    const int brow   = col0 + lbrow;
    const int bval   = (brow < N) ? 16 : 0;
    const __half* Asrc0 = Ah + (size_t)(row0 + larow) * K;
    const __half* Asrc1 = Asrc0 + aplane;
    const __half* Bsrc0 = Bh + (size_t)((brow < N) ? brow : 0) * K;
    const __half* Bsrc1 = Bsrc0 + bplane;

    const int la   = lane & 15;
    const int asel = lane >> 4;
    const int lb   = lane & 7;
    const int bsel = (lane >> 3) & 1;
    uint32_t aoff[2]; int ar7[2];
    #pragma unroll
    for (int mi = 0; mi < 2; mi++) {
        const int r = m_off + mi*16 + la;
        aoff[mi] = (uint32_t)r * 128;
        ar7[mi]  = r & 7;
    }
    uint32_t boff[NI]; int br7[NI];
    #pragma unroll
    for (int ni = 0; ni < NI; ni++) {
        const int r = n_off + ni*8 + lb;
        boff[ni] = (uint32_t)r * 128;
        br7[ni]  = r & 7;
    }

    const int nc = K >> 6;

    {
        const uint32_t sb = smb;
        #pragma unroll
        for (int j = 0; j < 2; j++) {
            const int ch = cbase + j;
            const uint32_t sw = (uint32_t)((ch ^ (larow & 7)) << 4);
            cpasync16(sb + larow*128 + sw,          Asrc0 + ch*8, 16);
            cpasync16(sb + APLANE + larow*128 + sw, Asrc1 + ch*8, 16);
        }
        #pragma unroll
        for (int j = 0; j < NI; j++) {
            const int ch = cbaseB + j;
            const uint32_t sw = (uint32_t)((ch ^ (lbrow & 7)) << 4);
            cpasync16(sb + 2*APLANE + lbrow*128 + sw,           Bsrc0 + ch*8, bval);
            cpasync16(sb + 2*APLANE + BPLANEx + lbrow*128 + sw, Bsrc1 + ch*8, bval);
        }
        asm volatile("cp.async.commit_group;\n");
    }

    for (int kc = 0; kc < nc; kc++) {
        if (kc + 1 < nc) {
            const int k0 = (kc + 1) << 6;
            const uint32_t sb = smb + ((kc + 1) & 1) * STAGE;
            #pragma unroll
            for (int j = 0; j < 2; j++) {
                const int ch = cbase + j;
                const uint32_t sw = (uint32_t)((ch ^ (larow & 7)) << 4);
                cpasync16(sb + larow*128 + sw,          Asrc0 + k0 + ch*8, 16);
                cpasync16(sb + APLANE + larow*128 + sw, Asrc1 + k0 + ch*8, 16);
            }
            #pragma unroll
            for (int j = 0; j < NI; j++) {
                const int ch = cbaseB + j;
                const uint32_t sw = (uint32_t)((ch ^ (lbrow & 7)) << 4);
                cpasync16(sb + 2*APLANE + lbrow*128 + sw,           Bsrc0 + k0 + ch*8, bval);
                cpasync16(sb + 2*APLANE + BPLANEx + lbrow*128 + sw, Bsrc1 + k0 + ch*8, bval);
            }
        }
        asm volatile("cp.async.commit_group;\n");
        asm volatile("cp.async.wait_group 1;\n");
        __syncthreads();

        const uint32_t S0 = smb + (kc & 1) * STAGE;
        const uint32_t S1 = S0 + APLANE;
        const uint32_t S2 = S0 + 2*APLANE;
        const uint32_t S3 = S2 + BPLANEx;

        #pragma unroll
        for (int s = 0; s < 4; s++) {
            uint32_t b0[NI][2], b1[NI][2];
            #pragma unroll
            for (int ni = 0; ni < NI; ni++) {
                const uint32_t swb = (uint32_t)(((2*s + bsel) ^ br7[ni]) << 4);
                ldsm2(b0[ni], S2 + boff[ni] + swb);
                ldsm2(b1[ni], S3 + boff[ni] + swb);
            }
            #pragma unroll
            for (int mi = 0; mi < 2; mi++) {
                const uint32_t swa = (uint32_t)(((2*s + asel) ^ ar7[mi]) << 4);
                uint32_t a0[4], a1[4];
                ldsm4(a0, S0 + aoff[mi] + swa);
                ldsm4(a1, S1 + aoff[mi] + swa);
                #pragma unroll
                for (int ni = 0; ni < NI; ni++) {
                    MMA16(c[mi][ni], a0, b0[ni]);
                    MMA16(c[mi][ni], a0, b1[ni]);
                    MMA16(c[mi][ni], a1, b0[ni]);
                }
            }
        }
        __syncthreads();
    }

    #pragma unroll
    for (int mi = 0; mi < 2; mi++) {
        #pragma unroll
        for (int half = 0; half < 2; half++) {
            const int r = row0 + m_off + mi*16 + gid + half*8;
            const int orow = (r / Tin) * Tout + toff + (r % Tin);
            #pragma unroll
            for (int ni = 0; ni < NI; ni++) {
                const int col = col0 + n_off + ni*8 + tg*2;
                if (col < N) {
                    float v0 = c[mi][ni][half*2 + 0];
                    float v1 = c[mi][ni][half*2 + 1];
                    if (bias) { v0 += bias[col]; v1 += bias[col+1]; }
                    float* dst = C + (size_t)orow * N + col;
                    if (accum) { v0 += dst[0]; v1 += dst[1]; }
                    *reinterpret_cast<float2*>(dst) = make_float2(v0, v1);
                }
            }
        }
    }
}

#define GSMEM4 (2*(2*APLANE + 2*128*128))
#define GSMEM2 (2*(2*APLANE + 2*64*128))

// ---------------- RMSNorm (fp32 out, final layer) ----------------
__global__ void rmsnorm_k(const float* __restrict__ x, const float* __restrict__ w,
                          float* __restrict__ out, int D)
{
    __shared__ float red[32];
    const int r = blockIdx.x;
    const float* xr = x + (size_t)r * D;
    float s = 0.f;
    for (int d = threadIdx.x; d < D; d += 256) { float v = xr[d]; s = fmaf(v, v, s); }
    const float tot = block_reduce_sum_256(s, red);
    const float rms = rsqrtf(tot / (float)D + 1e-5f);
    for (int d = threadIdx.x; d < D; d += 256)
        out[(size_t)r * D + d] = xr[d] * rms * w[d];
}

// ---------------- RMSNorm fused with fp16x2 split (D = 1024) ----------------
__global__ void rmsnorm_split_k(const float* __restrict__ x, const float* __restrict__ w,
                                __half* __restrict__ out, size_t S)
{
    __shared__ float red[32];
    const int r = blockIdx.x;
    const int tid = threadIdx.x;
    const float4 xv = *(const float4*)(x + (size_t)r * DMODEL + tid*4);
    const float4 wv = *(const float4*)(w + tid*4);
    float s = xv.x*xv.x + xv.y*xv.y + xv.z*xv.z + xv.w*xv.w;
    const float tot = block_reduce_sum_256(s, red);
    const float rms = rsqrtf(tot / (float)DMODEL + 1e-5f);
    float v0 = xv.x*rms*wv.x, v1 = xv.y*rms*wv.y, v2 = xv.z*rms*wv.z, v3 = xv.w*rms*wv.w;
    __half h0a, h1a, h0b, h1b, h0c, h1c, h0d, h1d;
    split2(v0, h0a, h1a); split2(v1, h0b, h1b);
    split2(v2, h0c, h1c); split2(v3, h0d, h1d);
    __half2* p0 = (__half2*)(out + (size_t)r * DMODEL);
    __half2* p1 = (__half2*)(out + S + (size_t)r * DMODEL);
    p0[tid*2]   = __halves2half2(h0a, h0b);
    p0[tid*2+1] = __halves2half2(h0c, h0d);
    p1[tid*2]   = __halves2half2(h1a, h1b);
    p1[tid*2+1] = __halves2half2(h1c, h1d);
}

// ---------------- precompute dt/da per (bh, t) ----------------
__global__ void dtda_k(const float* __restrict__ proj,
                       const float* __restrict__ dt_bias,
                       const float* __restrict__ A_log,
                       float* __restrict__ dtbuf,
                       float* __restrict__ dabuf)
{
    const int bh = blockIdx.x;
    const int b  = bh >> 5;
    const int h  = bh & 31;
    const int t  = threadIdx.x;          // 288
    const float vdt = proj[(size_t)(b*TSEQ + t)*PROJ_DIM + 2*DINNER + 2*NSTATE + h]
                    + dt_bias[h];
    const float dt = (vdt > 20.f) ? vdt : log1pf(expf(vdt));
    const float Aval = -expf(A_log[h]);
    dtbuf[bh*TSEQ + t] = dt;
    dabuf[bh*TSEQ + t] = expf(dt * Aval);
}

// ---------------- scan phase 1: two half-sequence local scans ----------------
#define SCX  0
#define SCB  64
#define SCC  192
#define SCDT 320
#define SCDA 321
__global__ void scan_p1(const float* __restrict__ proj,
                        const float* __restrict__ dtbuf,
                        const float* __restrict__ dabuf,
                        const float* __restrict__ Dssm,
                        float* __restrict__ yraw,
                        float* __restrict__ vstate,
                        float* __restrict__ cumP)
{
    const int bh   = blockIdx.x;
    const int ch   = blockIdx.y;            // 0 or 1
    const int b    = bh >> 5;
    const int h    = bh & 31;
    const int t0   = ch * CHUNK;
    const int t1   = t0 + CHUNK;
    const int tid  = threadIdx.x;
    const int warp = tid >> 5, lane = tid & 31;

    __shared__ float st[3][324];

    const float Dval = Dssm[h];

    float hs[8][4];
    #pragma unroll
    for (int i = 0; i < 8; i++)
        #pragma unroll
        for (int j = 0; j < 4; j++) hs[i][j] = 0.f;

    const int pbase = warp * 8;
    const int nbase = lane * 4;
    const bool s4 = (lane & 16) != 0;
    const bool s3 = (lane & 8)  != 0;
    const bool s2v = (lane & 4) != 0;
    const int  sidx = (lane >> 2) & 7;
    const bool swr  = ((lane & 3) == 0);

    float xprev[8], bprev[4], dtprev = 0.f;
    #pragma unroll
    for (int i = 0; i < 8; i++) xprev[i] = 0.f;
    #pragma unroll
    for (int j = 0; j < 4; j++) bprev[j] = 0.f;
    if (ch > 0) {
        const float* pp = proj + (size_t)(b * TSEQ + t0 - 1) * PROJ_DIM;
        #pragma unroll
        for (int i = 0; i < 8; i++) xprev[i] = pp[DINNER + h*PDIM + pbase + i];
        #pragma unroll
        for (int j = 0; j < 4; j++) bprev[j] = pp[2*DINNER + nbase + j];
        dtprev = dtbuf[bh * TSEQ + t0 - 1];
    }

    uint32_t stb[3];
    stb[0] = (uint32_t)__cvta_generic_to_shared(&st[0][0]);
    stb[1] = (uint32_t)__cvta_generic_to_shared(&st[1][0]);
    stb[2] = (uint32_t)__cvta_generic_to_shared(&st[2][0]);

    auto issue = [&](int buf, int t) {
        const float* pr = proj + (size_t)(b * TSEQ + t) * PROJ_DIM;
        const uint32_t base = stb[buf];
        if (tid < 16)
            cpasync16(base + (SCX + tid*4)*4,  pr + DINNER + h*PDIM + tid*4, 16);
        else if (tid < 48)
            cpasync16(base + (SCB + (tid-16)*4)*4, pr + 2*DINNER + (tid-16)*4, 16);
        else if (tid < 80)
            cpasync16(base + (SCC + (tid-48)*4)*4, pr + 2*DINNER + NSTATE + (tid-48)*4, 16);
        else if (tid == 80)
            cpasync4(base + SCDT*4, dtbuf + bh*TSEQ + t);
        else if (tid == 81)
            cpasync4(base + SCDA*4, dabuf + bh*TSEQ + t);
        asm volatile("cp.async.commit_group;\n");
    };

    issue(0, t0);
    issue(1, t0 + 1);

    float cum = 1.f;
    int buf = 0;
    for (int t = t0; t < t1; t++) {
        asm volatile("cp.async.wait_group 1;\n");
        __syncthreads();
        if (t + 2 < t1) {
            int nb = buf + 2; if (nb >= 3) nb -= 3;
            issue(nb, t + 2);
        } else {
            asm volatile("cp.async.commit_group;\n");
        }

        const float* sb = st[buf];
        const float dt  = sb[SCDT];
        const float da  = sb[SCDA];
        const float cu  = (1.f - ALPHA_C) * dt;
        const float cup = da * ALPHA_C * dtprev;
        if (ch == 1) {
            cum *= da;
            if (tid == 0) cumP[bh * TSEQ + t] = cum;
        }

        float bc[4], cc[4];
        #pragma unroll
        for (int j = 0; j < 4; j++) { bc[j] = sb[SCB + nbase + j]; cc[j] = sb[SCC + nbase + j]; }

        const int row = b * TSEQ + t;

        float v[8];
        #pragma unroll
        for (int i = 0; i < 8; i++) {
            const float xr  = sb[SCX + pbase + i];
            const float xpi = cup * xprev[i];
            const float xci = cu  * xr;
            float yp = 0.f;
            #pragma unroll
            for (int j = 0; j < 4; j++) {
                const float u = fmaf(xpi, bprev[j], xci * bc[j]);
                hs[i][j] = fmaf(da, hs[i][j], u);
                yp = fmaf(hs[i][j], cc[j], yp);
            }
            v[i] = yp;
            xprev[i] = xr;
        }

        float w4[4];
        #pragma unroll
        for (int i = 0; i < 4; i++) {
            const float send = s4 ? v[i]   : v[i+4];
            const float keep = s4 ? v[i+4] : v[i];
            w4[i] = keep + __shfl_xor_sync(0xffffffffu, send, 16);
        }
        float x2[2];
        #pragma unroll
        for (int i = 0; i < 2; i++) {
            const float send = s3 ? w4[i]   : w4[i+2];
            const float keep = s3 ? w4[i+2] : w4[i];
            x2[i] = keep + __shfl_xor_sync(0xffffffffu, send, 8);
        }
        float y;
        {
            const float send = s2v ? x2[0] : x2[1];
            const float keep = s2v ? x2[1] : x2[0];
            y = keep + __shfl_xor_sync(0xffffffffu, send, 4);
        }
        y += __shfl_xor_sync(0xffffffffu, y, 2);
        y += __shfl_xor_sync(0xffffffffu, y, 1);

        if (swr)
            yraw[(size_t)row * DINNER + h*PDIM + pbase + sidx] =
                fmaf(Dval, sb[SCX + pbase + sidx], y);

        #pragma unroll
        for (int j = 0; j < 4; j++) bprev[j] = bc[j];
        dtprev = dt;
        buf++; if (buf >= 3) buf = 0;
    }

    // chunk 0: store final state (= incoming state for chunk 1)
    if (ch == 0) {
        float* V = vstate + (size_t)bh * PNSZ;
        #pragma unroll
        for (int i = 0; i < 8; i++)
            #pragma unroll
            for (int j = 0; j < 4; j++)
                V[(pbase + i) * NSTATE + nbase + j] = hs[i][j];
    }
}

// ---------------- scan phase 3: y_t += P_t * (C_t . V0), second half only --------
__global__ void scan_p3(const float* __restrict__ proj,
                        const float* __restrict__ vstate,
                        const float* __restrict__ cumP,
                        float* __restrict__ yraw)
{
    const int bh   = blockIdx.x;
    const int b    = bh >> 5;
    const int h    = bh & 31;
    const int tid  = threadIdx.x;
    const int warp = tid >> 5, lane = tid & 31;
    const int pbase = warp * 8;
    const int nbase = lane * 4;
    const bool s4 = (lane & 16) != 0;
    const bool s3 = (lane & 8)  != 0;
    const bool s2v = (lane & 4) != 0;
    const int  sidx = (lane >> 2) & 7;
    const bool swr  = ((lane & 3) == 0);

    const float* V = vstate + (size_t)bh * PNSZ;
    float hin[8][4];
    #pragma unroll
    for (int i = 0; i < 8; i++) {
        const float4 q = *(const float4*)(V + (pbase + i) * NSTATE + nbase);
        hin[i][0] = q.x; hin[i][1] = q.y; hin[i][2] = q.z; hin[i][3] = q.w;
    }

    const int t0 = CHUNK + blockIdx.y * P3TS;
    for (int t = t0; t < t0 + P3TS; t++) {
        const int row = b * TSEQ + t;
        const float* pr = proj + (size_t)row * PROJ_DIM;
        const float Pt = cumP[bh * TSEQ + t];

        const float4 cq = *(const float4*)(pr + 2*DINNER + NSTATE + nbase);
        float cc[4] = {cq.x, cq.y, cq.z, cq.w};

        float v[8];
        #pragma unroll
        for (int i = 0; i < 8; i++) {
            float yp = 0.f;
            #pragma unroll
            for (int j = 0; j < 4; j++) yp = fmaf(hin[i][j], cc[j], yp);
            v[i] = yp;
        }

        float w4[4];
        #pragma unroll
        for (int i = 0; i < 4; i++) {
            const float send = s4 ? v[i]   : v[i+4];
            const float keep = s4 ? v[i+4] : v[i];
            w4[i] = keep + __shfl_xor_sync(0xffffffffu, send, 16);
        }
        float x2[2];
        #pragma unroll
        for (int i = 0; i < 2; i++) {
            const float send = s3 ? w4[i]   : w4[i+2];
            const float keep = s3 ? w4[i+2] : w4[i];
            x2[i] = keep + __shfl_xor_sync(0xffffffffu, send, 8);
        }
        float y;
        {
            const float send = s2v ? x2[0] : x2[1];
            const float keep = s2v ? x2[1] : x2[0];
            y = keep + __shfl_xor_sync(0xffffffffu, send, 4);
        }
        y += __shfl_xor_sync(0xffffffffu, y, 2);
        y += __shfl_xor_sync(0xffffffffu, y, 1);

        if (swr) {
            float* dst = yraw + (size_t)row * DINNER + h*PDIM + pbase + sidx;
            *dst = fmaf(Pt, y, *dst);
        }
    }
}

// ---------------- gate + gnorm fused with fp16x2 split (register-resident) --------
__global__ void gate_gnorm_split_k(const float* __restrict__ proj,
                                   const float* __restrict__ yraw,
                                   const float* __restrict__ gw,
                                   __half* __restrict__ out, size_t S)
{
    __shared__ float red[32];
    const int r = blockIdx.x;
    const int tid = threadIdx.x;
    const float* pz = proj + (size_t)r * PROJ_DIM;
    const float* yr = yraw + (size_t)r * DINNER;

    float g[2][4];
    float s = 0.f;
    #pragma unroll
    for (int it = 0; it < 2; it++) {
        const int d = (tid + it*256) * 4;
        const float4 zv = *(const float4*)(pz + d);
        const float4 yv = *(const float4*)(yr + d);
        g[it][0] = yv.x * zv.x / (1.f + expf(-zv.x));
        g[it][1] = yv.y * zv.y / (1.f + expf(-zv.y));
        g[it][2] = yv.z * zv.z / (1.f + expf(-zv.z));
        g[it][3] = yv.w * zv.w / (1.f + expf(-zv.w));
        s += g[it][0]*g[it][0] + g[it][1]*g[it][1] + g[it][2]*g[it][2] + g[it][3]*g[it][3];
    }
    const float tot = block_reduce_sum_256(s, red);
    const float rms = rsqrtf(tot / (float)DINNER + 1e-5f);

    __half2* p0 = (__half2*)(out + (size_t)r * DINNER);
    __half2* p1 = (__half2*)(out + S + (size_t)r * DINNER);
    #pragma unroll
    for (int it = 0; it < 2; it++) {
        const int d = (tid + it*256) * 4;
        const float4 wv = *(const float4*)(gw + d);
        float v0 = g[it][0]*rms*wv.x, v1 = g[it][1]*rms*wv.y;
        float v2 = g[it][2]*rms*wv.z, v3 = g[it][3]*rms*wv.w;
        __half h0a, h1a, h0b, h1b, h0c, h1c, h0d, h1d;
        split2(v0, h0a, h1a); split2(v1, h0b, h1b);
        split2(v2, h0c, h1c); split2(v3, h0d, h1d);
        p0[d/2]   = __halves2half2(h0a, h0b);
        p0[d/2+1] = __halves2half2(h0c, h0d);
        p1[d/2]   = __halves2half2(h1a, h1b);
        p1[d/2+1] = __halves2half2(h1c, h1d);
    }
}

// ---------------- mean over T per batch ----------------
__global__ void pool_k(const float* __restrict__ xin, float* __restrict__ pooled)
{
    const int b = blockIdx.x;
    const int d = blockIdx.y * 256 + threadIdx.x;
    float s = 0.f;
    for (int t = 0; t < TSEQ; t++)
        s += xin[(size_t)(b*TSEQ + t) * DMODEL + d];
    pooled[b*DMODEL + d] = s * (1.f / (float)TSEQ);
}

// ---------------- head GEMM + bias + L2-normalize ----------------
__global__ void head_k(const float* __restrict__ pooled,
                       const float* __restrict__ hw,
                       const float* __restrict__ hb,
                       float* __restrict__ out)
{
    __shared__ float sp[DMODEL];
    __shared__ float so[EDIM];
    __shared__ float red[32];
    const int b = blockIdx.x;

    for (int d = threadIdx.x; d < DMODEL; d += 256) sp[d] = pooled[b*DMODEL + d];
    __syncthreads();

    float acc[EDIM/256];
    #pragma unroll
    for (int m = 0; m < EDIM/256; m++) acc[m] = hb[threadIdx.x + m*256];
    for (int k = 0; k < DMODEL; k++) {
        const float p = sp[k];
        #pragma unroll
        for (int m = 0; m < EDIM/256; m++)
            acc[m] = fmaf(p, hw[(size_t)k*EDIM + threadIdx.x + m*256], acc[m]);
    }
    #pragma unroll
    for (int m = 0; m < EDIM/256; m++) so[threadIdx.x + m*256] = acc[m];
    __syncthreads();

    float s = 0.f;
    for (int e = threadIdx.x; e < EDIM; e += 256) s = fmaf(so[e], so[e], s);
    const float tot = block_reduce_sum_256(s, red);
    const float inv = 1.f / fmaxf(sqrtf(tot), 1e-12f);
    for (int e = threadIdx.x; e < EDIM; e += 256)
        out[(size_t)b*EDIM + e] = so[e] * inv;
}

// ---------------- host launcher ----------------
extern "C" void kernel_launch(void* const* d_in, const int* in_sizes, int n_in,
                              void* d_out, int out_size)
{
    const float* visual   = (const float*)d_in[0];
    const float* query    = (const float*)d_in[1];
    const float* vis_w    = (const float*)d_in[2];
    const float* vis_b    = (const float*)d_in[3];
    const float* qry_w    = (const float*)d_in[4];
    const float* qry_b    = (const float*)d_in[5];
    const float* norm_ws  = (const float*)d_in[6];
    const float* in_ws    = (const float*)d_in[7];
    const float* dt_bias  = (const float*)d_in[8];
    const float* A_logs   = (const float*)d_in[9];
    const float* D_ssm    = (const float*)d_in[10];
    const float* gnorm_ws = (const float*)d_in[11];
    const float* out_ws   = (const float*)d_in[12];
    const float* norm_f_w = (const float*)d_in[13];
    const float* head_w   = (const float*)d_in[14];
    const float* head_b   = (const float*)d_in[15];
    float* out = (float*)d_out;

    float *hidden, *xin, *proj, *yraw, *pooled, *vstate, *cumP, *dtb, *dab;
    __half *ah, *bw;
    cudaGetSymbolAddress((void**)&hidden, g_hidden);
    cudaGetSymbolAddress((void**)&xin,    g_xin);
    cudaGetSymbolAddress((void**)&proj,   g_proj);
    cudaGetSymbolAddress((void**)&yraw,   g_yraw);
    cudaGetSymbolAddress((void**)&pooled, g_pooled);
    cudaGetSymbolAddress((void**)&vstate, g_vstate);
    cudaGetSymbolAddress((void**)&cumP,   g_cumP);
    cudaGetSymbolAddress((void**)&dtb,    g_dt);
    cudaGetSymbolAddress((void**)&dab,    g_da);
    cudaGetSymbolAddress((void**)&ah,     g_ah);
    cudaGetSymbolAddress((void**)&bw,     g_bw);

    cudaFuncSetAttribute(hgemm_t<4>, cudaFuncAttributeMaxDynamicSharedMemorySize, GSMEM4);
    cudaFuncSetAttribute(hgemm_t<2>, cudaFuncAttributeMaxDynamicSharedMemorySize, GSMEM2);

    const dim3 blk(256);

    cudaStream_t s2;
    cudaStreamCreateWithFlags(&s2, cudaStreamNonBlocking);
    cudaEvent_t evFork, evS[NLAYERS], evP[NLAYERS];
    cudaEventCreateWithFlags(&evFork, cudaEventDisableTiming);
    for (int i = 0; i < NLAYERS; i++) {
        cudaEventCreateWithFlags(&evS[i], cudaEventDisableTiming);
        cudaEventCreateWithFlags(&evP[i], cudaEventDisableTiming);
    }

    auto slice = [&](int i) -> __half* { return bw + W_L_OFF + (size_t)(i & 1) * W_L_SZ; };

    cudaEventRecord(evFork, 0);
    cudaStreamWaitEvent(s2, evFork, 0);
    tsplit2f<<<dim3(PROJ_DIM/32, DMODEL/64), blk, 0, s2>>>(in_ws, slice(0), DMODEL, PROJ_DIM);
    tsplit2f<<<dim3(DMODEL/32, DINNER/64), blk, 0, s2>>>(out_ws, slice(0) + 2*W_IN_PL, DINNER, DMODEL);
    cudaEventRecord(evP[0], s2);

    // ---- initial projections into hidden[b, t, :] ----
    {
        const size_t S = (size_t)BATCH*TVIS*DMODEL;
        split2_x<<<(unsigned)((S + 255)/256), blk>>>(visual, ah, S);
        tsplit2f<<<dim3(DMODEL/32, DMODEL/64), blk>>>(vis_w, bw + W_VIS_OFF, DMODEL, DMODEL);
        hgemm_t<2><<<dim3(DMODEL/64, (BATCH*TVIS)/64), blk, GSMEM2>>>(
            ah, S, bw + W_VIS_OFF, W_VIS_PL, hidden,
            BATCH*TVIS, DMODEL, DMODEL, vis_b, 0, TVIS, TSEQ, 0);
    }
    {
        const size_t S = (size_t)BATCH*TQRY*DMODEL;
        split2_x<<<(unsigned)((S + 255)/256), blk>>>(query, ah, S);
        tsplit2f<<<dim3(DMODEL/32, DMODEL/64), blk>>>(qry_w, bw + W_QRY_OFF, DMODEL, DMODEL);
        hgemm_t<2><<<dim3(DMODEL/64, (BATCH*TQRY)/64), blk, GSMEM2>>>(
            ah, S, bw + W_QRY_OFF, W_VIS_PL, hidden,
            BATCH*TQRY, DMODEL, DMODEL, qry_b, 0, TQRY, TSEQ, TVIS);
    }

    for (int i = 0; i < NLAYERS; i++) {
        const size_t SA = (size_t)ROWS*DMODEL;
        rmsnorm_split_k<<<ROWS, blk>>>(hidden, norm_ws + (size_t)i*DMODEL, ah, SA);

        cudaStreamWaitEvent(0, evP[i], 0);
        hgemm_t<4><<<dim3((PROJ_DIM + 127)/128, ROWS/64), blk, GSMEM4>>>(
            ah, SA, slice(i), W_IN_PL, proj,
            ROWS, PROJ_DIM, DMODEL, nullptr, 0, ROWS, ROWS, 0);

        // precompute dt/da, then 2-chunk scan
        dtda_k<<<NBH, TSEQ>>>(proj, dt_bias + (size_t)i*NHEADS,
                              A_logs + (size_t)i*NHEADS, dtb, dab);
        scan_p1<<<dim3(NBH, 2), blk>>>(
            proj, dtb, dab, D_ssm + (size_t)i*NHEADS, yraw, vstate, cumP);
        cudaEventRecord(evS[i], 0);

        if (i + 1 < NLAYERS) {
            cudaStreamWaitEvent(s2, evS[i], 0);
            tsplit2f<<<dim3(PROJ_DIM/32, DMODEL/64), blk, 0, s2>>>(
                in_ws + (size_t)(i+1)*DMODEL*PROJ_DIM, slice(i+1), DMODEL, PROJ_DIM);
            tsplit2f<<<dim3(DMODEL/32, DINNER/64), blk, 0, s2>>>(
                out_ws + (size_t)(i+1)*DINNER*DMODEL, slice(i+1) + 2*W_IN_PL, DINNER, DMODEL);
            cudaEventRecord(evP[i+1], s2);
        }

        scan_p3<<<dim3(NBH, CHUNK/P3TS), blk>>>(proj, vstate, cumP, yraw);

        const size_t SG = (size_t)ROWS*DINNER;
        gate_gnorm_split_k<<<ROWS, blk>>>(proj, yraw, gnorm_ws + (size_t)i*DINNER, ah, SG);

        hgemm_t<2><<<dim3(DMODEL/64, ROWS/64), blk, GSMEM2>>>(
            ah, SG, slice(i) + 2*W_IN_PL, W_OUT_PL, hidden,
            ROWS, DMODEL, DINNER, nullptr, 1, ROWS, ROWS, 0);
    }

    rmsnorm_k<<<ROWS, blk>>>(hidden, norm_f_w, xin, DMODEL);
    pool_k<<<dim3(BATCH, DMODEL/256), blk>>>(xin, pooled);
    head_k<<<BATCH, blk>>>(pooled, head_w, head_b, out);
}

// round 16
// speedup vs baseline: 1.1488x; 1.0292x over previous
#include <cuda_runtime.h>
#include <cuda_fp16.h>
#include <math.h>
#include <stdint.h>

// ---------------- problem constants ----------------
#define BATCH   4
#define TSEQ    288
#define TVIS    256
#define TQRY    32
#define DMODEL  1024
#define DINNER  2048
#define NHEADS  32
#define NSTATE  128
#define PDIM    64
#define NLAYERS 12
#define PROJ_DIM 4384
#define EDIM    1536
#define ROWS    (BATCH*TSEQ)    // 1152
#define ALPHA_C 0.5f
#define NBH     (BATCH*NHEADS)  // 128
#define CHUNK   144             // 2 chunks of 144
#define P3TS    16              // 144 = 9*16
#define PNSZ    (PDIM*NSTATE)

// weight-slice geometry (halves)
#define W_VIS_OFF   0ull
#define W_VIS_PL    (1024ull*1024ull)
#define W_QRY_OFF   (2ull*W_VIS_PL)
#define W_L_OFF     (4ull*W_VIS_PL)
#define W_IN_PL     ((size_t)DMODEL*PROJ_DIM)
#define W_OUT_PL    ((size_t)DINNER*DMODEL)
#define W_L_SZ      (2ull*W_IN_PL + 2ull*W_OUT_PL)
#define W_TOTAL     (W_L_OFF + 2ull*W_L_SZ)

// ---------------- scratch (device globals; no allocation) ----------------
__device__ float g_hidden[ROWS*DMODEL];
__device__ float g_xin   [ROWS*DMODEL];
__device__ float g_proj  [ROWS*PROJ_DIM];
__device__ float g_yraw  [ROWS*DINNER];
__device__ float g_pooled[BATCH*DMODEL];
__device__ float g_vstate[(size_t)NBH*PNSZ];
__device__ float g_cumP  [NBH*TSEQ];
__device__ __align__(16) __half g_ah[2ull*1152*2048];
__device__ __align__(16) __half g_bw[W_TOTAL];

// ---------------- helpers ----------------
__device__ __forceinline__ float block_reduce_sum_256(float v, float* red)
{
    #pragma unroll
    for (int o = 16; o; o >>= 1) v += __shfl_xor_sync(0xffffffffu, v, o);
    const int warp = threadIdx.x >> 5, lane = threadIdx.x & 31;
    if (lane == 0) red[warp] = v;
    __syncthreads();
    if (threadIdx.x < 32) {
        float t = (threadIdx.x < 8) ? red[threadIdx.x] : 0.f;
        #pragma unroll
        for (int o = 4; o; o >>= 1) t += __shfl_xor_sync(0xffffffffu, t, o);
        if (threadIdx.x == 0) red[0] = t;
    }
    __syncthreads();
    return red[0];
}

__device__ __forceinline__ void split2(float x, __half& h0, __half& h1)
{
    h0 = __float2half_rn(x);
    h1 = __float2half_rn(x - __half2float(h0));
}

#define MMA16(cc, aa, bb)                                                        \
  asm volatile("mma.sync.aligned.m16n8k16.row.col.f32.f16.f16.f32 "             \
    "{%0,%1,%2,%3}, {%4,%5,%6,%7}, {%8,%9}, {%0,%1,%2,%3};\n"                    \
    : "+f"((cc)[0]), "+f"((cc)[1]), "+f"((cc)[2]), "+f"((cc)[3])                 \
    : "r"((aa)[0]), "r"((aa)[1]), "r"((aa)[2]), "r"((aa)[3]),                    \
      "r"((bb)[0]), "r"((bb)[1]))

__device__ __forceinline__ void ldsm4(uint32_t* r, uint32_t addr)
{
    asm volatile("ldmatrix.sync.aligned.m8n8.x4.shared.b16 {%0,%1,%2,%3}, [%4];"
                 : "=r"(r[0]), "=r"(r[1]), "=r"(r[2]), "=r"(r[3]) : "r"(addr));
}
__device__ __forceinline__ void ldsm2(uint32_t* r, uint32_t addr)
{
    asm volatile("ldmatrix.sync.aligned.m8n8.x2.shared.b16 {%0,%1}, [%2];"
                 : "=r"(r[0]), "=r"(r[1]) : "r"(addr));
}

__device__ __forceinline__ void cpasync16(uint32_t dst, const void* src, int sz)
{
    asm volatile("cp.async.cg.shared.global [%0], [%1], 16, %2;\n"
                 :: "r"(dst), "l"(src), "r"(sz));
}

// ---------------- prep: split fp32 -> 2 fp16 planes ----------------
__global__ void split2_x(const float* __restrict__ x, __half* __restrict__ out, size_t S)
{
    size_t i = (size_t)blockIdx.x * blockDim.x + threadIdx.x;
    if (i < S) {
        __half h0, h1; split2(x[i], h0, h1);
        out[i] = h0; out[S + i] = h1;
    }
}

// ---------------- prep: transpose KxN fp32 -> 2 planes [N][K] fp16 ----------------
__global__ void tsplit2f(const float* __restrict__ W, __half* __restrict__ out,
                         int K, int N)
{
    __shared__ float tile[64][33];
    const int n0 = blockIdx.x * 32, k0 = blockIdx.y * 64;
    const int tid = threadIdx.x;
    const int r = tid >> 5, c = tid & 31;
    #pragma unroll
    for (int i = 0; i < 8; i++)
        tile[i*8 + r][c] = W[(size_t)(k0 + i*8 + r) * N + n0 + c];
    __syncthreads();

    const size_t NK = (size_t)N * K;
    const int ns = tid >> 5;
    const int kp = tid & 31;
    #pragma unroll
    for (int j = 0; j < 4; j++) {
        const int nl = j*8 + ns;
        const int n  = n0 + nl;
        const float f0 = tile[2*kp    ][nl];
        const float f1 = tile[2*kp + 1][nl];
        __half a0, a1, b0, b1;
        split2(f0, a0, a1);
        split2(f1, b0, b1);
        __half2* p0 = (__half2*)(out + (size_t)n * K + k0);
        __half2* p1 = (__half2*)(out + NK + (size_t)n * K + k0);
        p0[kp] = __halves2half2(a0, b0);
        p1[kp] = __halves2half2(a1, b1);
    }
}

// ---------------- fp16x2 mma.sync GEMM, BM=64, BN=32*NI, 2 CTAs/SM ----------------
#define APLANE 8192
template<int NI>
__global__ __launch_bounds__(256, 2)
void hgemm_t(const __half* __restrict__ Ah, size_t aplane,
             const __half* __restrict__ Bh, size_t bplane,
             float* __restrict__ C, int M, int N, int K,
             const float* __restrict__ bias, int accum,
             int Tin, int Tout, int toff)
{
    constexpr int BN      = 32 * NI;
    constexpr int BPLANEx = BN * 128;
    constexpr int STAGE   = 2*APLANE + 2*BPLANEx;
    constexpr int TPB     = 256 / BN;

    extern __shared__ char sm[];
    const uint32_t smb = (uint32_t)__cvta_generic_to_shared(sm);

    const int tid  = threadIdx.x;
    const int warp = tid >> 5, lane = tid & 31;
    const int gid  = lane >> 2, tg = lane & 3;
    const int row0 = blockIdx.y * 64;
    const int col0 = blockIdx.x * BN;
    const int m_off = (warp & 1) * 32;
    const int n_off = (warp >> 1) * (8 * NI);

    float c[2][NI][4];
    #pragma unroll
    for (int mi = 0; mi < 2; mi++)
        #pragma unroll
        for (int ni = 0; ni < NI; ni++)
            #pragma unroll
            for (int q = 0; q < 4; q++) c[mi][ni][q] = 0.f;

    const int larow  = tid >> 2;
    const int cbase  = (tid & 3) * 2;
    const int lbrow  = tid / TPB;
    const int cbaseB = (tid % TPB) * NI;
    const int brow   = col0 + lbrow;
    const int bval   = (brow < N) ? 16 : 0;
    const __half* Asrc0 = Ah + (size_t)(row0 + larow) * K;
    const __half* Asrc1 = Asrc0 + aplane;
    const __half* Bsrc0 = Bh + (size_t)((brow < N) ? brow : 0) * K;
    const __half* Bsrc1 = Bsrc0 + bplane;

    const int la   = lane & 15;
    const int asel = lane >> 4;
    const int lb   = lane & 7;
    const int bsel = (lane >> 3) & 1;
    uint32_t aoff[2]; int ar7[2];
    #pragma unroll
    for (int mi = 0; mi < 2; mi++) {
        const int r = m_off + mi*16 + la;
        aoff[mi] = (uint32_t)r * 128;
        ar7[mi]  = r & 7;
    }
    uint32_t boff[NI]; int br7[NI];
    #pragma unroll
    for (int ni = 0; ni < NI; ni++) {
        const int r = n_off + ni*8 + lb;
        boff[ni] = (uint32_t)r * 128;
        br7[ni]  = r & 7;
    }

    const int nc = K >> 6;

    {
        const uint32_t sb = smb;
        #pragma unroll
        for (int j = 0; j < 2; j++) {
            const int ch = cbase + j;
            const uint32_t sw = (uint32_t)((ch ^ (larow & 7)) << 4);
            cpasync16(sb + larow*128 + sw,          Asrc0 + ch*8, 16);
            cpasync16(sb + APLANE + larow*128 + sw, Asrc1 + ch*8, 16);
        }
        #pragma unroll
        for (int j = 0; j < NI; j++) {
            const int ch = cbaseB + j;
            const uint32_t sw = (uint32_t)((ch ^ (lbrow & 7)) << 4);
            cpasync16(sb + 2*APLANE + lbrow*128 + sw,           Bsrc0 + ch*8, bval);
            cpasync16(sb + 2*APLANE + BPLANEx + lbrow*128 + sw, Bsrc1 + ch*8, bval);
        }
        asm volatile("cp.async.commit_group;\n");
    }

    for (int kc = 0; kc < nc; kc++) {
        if (kc + 1 < nc) {
            const int k0 = (kc + 1) << 6;
            const uint32_t sb = smb + ((kc + 1) & 1) * STAGE;
            #pragma unroll
            for (int j = 0; j < 2; j++) {
                const int ch = cbase + j;
                const uint32_t sw = (uint32_t)((ch ^ (larow & 7)) << 4);
                cpasync16(sb + larow*128 + sw,          Asrc0 + k0 + ch*8, 16);
                cpasync16(sb + APLANE + larow*128 + sw, Asrc1 + k0 + ch*8, 16);
            }
            #pragma unroll
            for (int j = 0; j < NI; j++) {
                const int ch = cbaseB + j;
                const uint32_t sw = (uint32_t)((ch ^ (lbrow & 7)) << 4);
                cpasync16(sb + 2*APLANE + lbrow*128 + sw,           Bsrc0 + k0 + ch*8, bval);
                cpasync16(sb + 2*APLANE + BPLANEx + lbrow*128 + sw, Bsrc1 + k0 + ch*8, bval);
            }
        }
        asm volatile("cp.async.commit_group;\n");
        asm volatile("cp.async.wait_group 1;\n");
        __syncthreads();

        const uint32_t S0 = smb + (kc & 1) * STAGE;
        const uint32_t S1 = S0 + APLANE;
        const uint32_t S2 = S0 + 2*APLANE;
        const uint32_t S3 = S2 + BPLANEx;

        #pragma unroll
        for (int s = 0; s < 4; s++) {
            uint32_t b0[NI][2], b1[NI][2];
            #pragma unroll
            for (int ni = 0; ni < NI; ni++) {
                const uint32_t swb = (uint32_t)(((2*s + bsel) ^ br7[ni]) << 4);
                ldsm2(b0[ni], S2 + boff[ni] + swb);
                ldsm2(b1[ni], S3 + boff[ni] + swb);
            }
            #pragma unroll
            for (int mi = 0; mi < 2; mi++) {
                const uint32_t swa = (uint32_t)(((2*s + asel) ^ ar7[mi]) << 4);
                uint32_t a0[4], a1[4];
                ldsm4(a0, S0 + aoff[mi] + swa);
                ldsm4(a1, S1 + aoff[mi] + swa);
                #pragma unroll
                for (int ni = 0; ni < NI; ni++) {
                    MMA16(c[mi][ni], a0, b0[ni]);
                    MMA16(c[mi][ni], a0, b1[ni]);
                    MMA16(c[mi][ni], a1, b0[ni]);
                }
            }
        }
        __syncthreads();
    }

    #pragma unroll
    for (int mi = 0; mi < 2; mi++) {
        #pragma unroll
        for (int half = 0; half < 2; half++) {
            const int r = row0 + m_off + mi*16 + gid + half*8;
            const int orow = (r / Tin) * Tout + toff + (r % Tin);
            #pragma unroll
            for (int ni = 0; ni < NI; ni++) {
                const int col = col0 + n_off + ni*8 + tg*2;
                if (col < N) {
                    float v0 = c[mi][ni][half*2 + 0];
                    float v1 = c[mi][ni][half*2 + 1];
                    if (bias) { v0 += bias[col]; v1 += bias[col+1]; }
                    float* dst = C + (size_t)orow * N + col;
                    if (accum) { v0 += dst[0]; v1 += dst[1]; }
                    *reinterpret_cast<float2*>(dst) = make_float2(v0, v1);
                }
            }
        }
    }
}

#define GSMEM4 (2*(2*APLANE + 2*128*128))
#define GSMEM2 (2*(2*APLANE + 2*64*128))

// ---------------- RMSNorm (fp32 out, final layer) ----------------
__global__ void rmsnorm_k(const float* __restrict__ x, const float* __restrict__ w,
                          float* __restrict__ out, int D)
{
    __shared__ float red[32];
    const int r = blockIdx.x;
    const float* xr = x + (size_t)r * D;
    float s = 0.f;
    for (int d = threadIdx.x; d < D; d += 256) { float v = xr[d]; s = fmaf(v, v, s); }
    const float tot = block_reduce_sum_256(s, red);
    const float rms = rsqrtf(tot / (float)D + 1e-5f);
    for (int d = threadIdx.x; d < D; d += 256)
        out[(size_t)r * D + d] = xr[d] * rms * w[d];
}

// ---------------- RMSNorm fused with fp16x2 split (D = 1024) ----------------
__global__ void rmsnorm_split_k(const float* __restrict__ x, const float* __restrict__ w,
                                __half* __restrict__ out, size_t S)
{
    __shared__ float red[32];
    const int r = blockIdx.x;
    const int tid = threadIdx.x;
    const float4 xv = *(const float4*)(x + (size_t)r * DMODEL + tid*4);
    const float4 wv = *(const float4*)(w + tid*4);
    float s = xv.x*xv.x + xv.y*xv.y + xv.z*xv.z + xv.w*xv.w;
    const float tot = block_reduce_sum_256(s, red);
    const float rms = rsqrtf(tot / (float)DMODEL + 1e-5f);
    float v0 = xv.x*rms*wv.x, v1 = xv.y*rms*wv.y, v2 = xv.z*rms*wv.z, v3 = xv.w*rms*wv.w;
    __half h0a, h1a, h0b, h1b, h0c, h1c, h0d, h1d;
    split2(v0, h0a, h1a); split2(v1, h0b, h1b);
    split2(v2, h0c, h1c); split2(v3, h0d, h1d);
    __half2* p0 = (__half2*)(out + (size_t)r * DMODEL);
    __half2* p1 = (__half2*)(out + S + (size_t)r * DMODEL);
    p0[tid*2]   = __halves2half2(h0a, h0b);
    p0[tid*2+1] = __halves2half2(h0c, h0d);
    p1[tid*2]   = __halves2half2(h1a, h1b);
    p1[tid*2+1] = __halves2half2(h1c, h1d);
}

// ---------------- scan phase 1: two half-sequence local scans ----------------
// dt/da computed in-CTA (prologue, parallel over steps) — no separate kernel.
#define SCX  0
#define SCB  64
#define SCC  192
__global__ void scan_p1(const float* __restrict__ proj,
                        const float* __restrict__ dt_bias,
                        const float* __restrict__ A_log,
                        const float* __restrict__ Dssm,
                        float* __restrict__ yraw,
                        float* __restrict__ vstate,
                        float* __restrict__ cumP)
{
    const int bh   = blockIdx.x;
    const int ch   = blockIdx.y;            // 0 or 1
    const int b    = bh >> 5;
    const int h    = bh & 31;
    const int t0   = ch * CHUNK;
    const int t1   = t0 + CHUNK;
    const int tid  = threadIdx.x;
    const int warp = tid >> 5, lane = tid & 31;

    __shared__ float st[3][324];
    __shared__ float sdt[CHUNK];
    __shared__ float sda[CHUNK];
    __shared__ float sdtprev;

    const float dtb  = dt_bias[h];
    const float Aval = -expf(A_log[h]);
    const float Dval = Dssm[h];

    // prologue: dt/da for this chunk, computed in parallel (same formulas/order as before)
    if (tid < CHUNK) {
        const float vdt = proj[(size_t)(b*TSEQ + t0 + tid)*PROJ_DIM + 2*DINNER + 2*NSTATE + h] + dtb;
        const float dt = (vdt > 20.f) ? vdt : log1pf(expf(vdt));
        sdt[tid] = dt;
        sda[tid] = expf(dt * Aval);
    }
    if (tid == 255) {
        float v = 0.f;
        if (ch > 0) {
            const float vdt = proj[(size_t)(b*TSEQ + t0 - 1)*PROJ_DIM + 2*DINNER + 2*NSTATE + h] + dtb;
            v = (vdt > 20.f) ? vdt : log1pf(expf(vdt));
        }
        sdtprev = v;
    }

    float hs[8][4];
    #pragma unroll
    for (int i = 0; i < 8; i++)
        #pragma unroll
        for (int j = 0; j < 4; j++) hs[i][j] = 0.f;

    const int pbase = warp * 8;
    const int nbase = lane * 4;
    const bool s4 = (lane & 16) != 0;
    const bool s3 = (lane & 8)  != 0;
    const bool s2v = (lane & 4) != 0;
    const int  sidx = (lane >> 2) & 7;
    const bool swr  = ((lane & 3) == 0);

    float xprev[8], bprev[4];
    #pragma unroll
    for (int i = 0; i < 8; i++) xprev[i] = 0.f;
    #pragma unroll
    for (int j = 0; j < 4; j++) bprev[j] = 0.f;
    if (ch > 0) {
        const float* pp = proj + (size_t)(b * TSEQ + t0 - 1) * PROJ_DIM;
        #pragma unroll
        for (int i = 0; i < 8; i++) xprev[i] = pp[DINNER + h*PDIM + pbase + i];
        #pragma unroll
        for (int j = 0; j < 4; j++) bprev[j] = pp[2*DINNER + nbase + j];
    }

    uint32_t stb[3];
    stb[0] = (uint32_t)__cvta_generic_to_shared(&st[0][0]);
    stb[1] = (uint32_t)__cvta_generic_to_shared(&st[1][0]);
    stb[2] = (uint32_t)__cvta_generic_to_shared(&st[2][0]);

    auto issue = [&](int buf, int t) {
        const float* pr = proj + (size_t)(b * TSEQ + t) * PROJ_DIM;
        const uint32_t base = stb[buf];
        if (tid < 16)
            cpasync16(base + (SCX + tid*4)*4,  pr + DINNER + h*PDIM + tid*4, 16);
        else if (tid < 48)
            cpasync16(base + (SCB + (tid-16)*4)*4, pr + 2*DINNER + (tid-16)*4, 16);
        else if (tid < 80)
            cpasync16(base + (SCC + (tid-48)*4)*4, pr + 2*DINNER + NSTATE + (tid-48)*4, 16);
        asm volatile("cp.async.commit_group;\n");
    };

    issue(0, t0);
    issue(1, t0 + 1);

    __syncthreads();                  // order prologue smem writes vs reads
    float dtprev = sdtprev;

    float cum = 1.f;
    int buf = 0;
    for (int t = t0; t < t1; t++) {
        asm volatile("cp.async.wait_group 1;\n");
        __syncthreads();
        if (t + 2 < t1) {
            int nb = buf + 2; if (nb >= 3) nb -= 3;
            issue(nb, t + 2);
        } else {
            asm volatile("cp.async.commit_group;\n");
        }

        const float* sb = st[buf];
        const float dt  = sdt[t - t0];
        const float da  = sda[t - t0];
        const float cu  = (1.f - ALPHA_C) * dt;
        const float cup = da * ALPHA_C * dtprev;
        if (ch == 1) {
            cum *= da;
            if (tid == 0) cumP[bh * TSEQ + t] = cum;
        }

        float bc[4], cc[4];
        #pragma unroll
        for (int j = 0; j < 4; j++) { bc[j] = sb[SCB + nbase + j]; cc[j] = sb[SCC + nbase + j]; }

        const int row = b * TSEQ + t;

        float v[8];
        #pragma unroll
        for (int i = 0; i < 8; i++) {
            const float xr  = sb[SCX + pbase + i];
            const float xpi = cup * xprev[i];
            const float xci = cu  * xr;
            float yp = 0.f;
            #pragma unroll
            for (int j = 0; j < 4; j++) {
                const float u = fmaf(xpi, bprev[j], xci * bc[j]);
                hs[i][j] = fmaf(da, hs[i][j], u);
                yp = fmaf(hs[i][j], cc[j], yp);
            }
            v[i] = yp;
            xprev[i] = xr;
        }

        float w4[4];
        #pragma unroll
        for (int i = 0; i < 4; i++) {
            const float send = s4 ? v[i]   : v[i+4];
            const float keep = s4 ? v[i+4] : v[i];
            w4[i] = keep + __shfl_xor_sync(0xffffffffu, send, 16);
        }
        float x2[2];
        #pragma unroll
        for (int i = 0; i < 2; i++) {
            const float send = s3 ? w4[i]   : w4[i+2];
            const float keep = s3 ? w4[i+2] : w4[i];
            x2[i] = keep + __shfl_xor_sync(0xffffffffu, send, 8);
        }
        float y;
        {
            const float send = s2v ? x2[0] : x2[1];
            const float keep = s2v ? x2[1] : x2[0];
            y = keep + __shfl_xor_sync(0xffffffffu, send, 4);
        }
        y += __shfl_xor_sync(0xffffffffu, y, 2);
        y += __shfl_xor_sync(0xffffffffu, y, 1);

        if (swr)
            yraw[(size_t)row * DINNER + h*PDIM + pbase + sidx] =
                fmaf(Dval, sb[SCX + pbase + sidx], y);

        #pragma unroll
        for (int j = 0; j < 4; j++) bprev[j] = bc[j];
        dtprev = dt;
        buf++; if (buf >= 3) buf = 0;
    }

    // chunk 0: store final state (= incoming state for chunk 1)
    if (ch == 0) {
        float* V = vstate + (size_t)bh * PNSZ;
        #pragma unroll
        for (int i = 0; i < 8; i++)
            #pragma unroll
            for (int j = 0; j < 4; j++)
                V[(pbase + i) * NSTATE + nbase + j] = hs[i][j];
    }
}

// ---------------- scan phase 3: y_t += P_t * (C_t . V0), second half only --------
__global__ void scan_p3(const float* __restrict__ proj,
                        const float* __restrict__ vstate,
                        const float* __restrict__ cumP,
                        float* __restrict__ yraw)
{
    const int bh   = blockIdx.x;
    const int b    = bh >> 5;
    const int h    = bh & 31;
    const int tid  = threadIdx.x;
    const int warp = tid >> 5, lane = tid & 31;
    const int pbase = warp * 8;
    const int nbase = lane * 4;
    const bool s4 = (lane & 16) != 0;
    const bool s3 = (lane & 8)  != 0;
    const bool s2v = (lane & 4) != 0;
    const int  sidx = (lane >> 2) & 7;
    const bool swr  = ((lane & 3) == 0);

    const float* V = vstate + (size_t)bh * PNSZ;
    float hin[8][4];
    #pragma unroll
    for (int i = 0; i < 8; i++) {
        const float4 q = *(const float4*)(V + (pbase + i) * NSTATE + nbase);
        hin[i][0] = q.x; hin[i][1] = q.y; hin[i][2] = q.z; hin[i][3] = q.w;
    }

    const int t0 = CHUNK + blockIdx.y * P3TS;
    for (int t = t0; t < t0 + P3TS; t++) {
        const int row = b * TSEQ + t;
        const float* pr = proj + (size_t)row * PROJ_DIM;
        const float Pt = cumP[bh * TSEQ + t];

        const float4 cq = *(const float4*)(pr + 2*DINNER + NSTATE + nbase);
        float cc[4] = {cq.x, cq.y, cq.z, cq.w};

        float v[8];
        #pragma unroll
        for (int i = 0; i < 8; i++) {
            float yp = 0.f;
            #pragma unroll
            for (int j = 0; j < 4; j++) yp = fmaf(hin[i][j], cc[j], yp);
            v[i] = yp;
        }

        float w4[4];
        #pragma unroll
        for (int i = 0; i < 4; i++) {
            const float send = s4 ? v[i]   : v[i+4];
            const float keep = s4 ? v[i+4] : v[i];
            w4[i] = keep + __shfl_xor_sync(0xffffffffu, send, 16);
        }
        float x2[2];
        #pragma unroll
        for (int i = 0; i < 2; i++) {
            const float send = s3 ? w4[i]   : w4[i+2];
            const float keep = s3 ? w4[i+2] : w4[i];
            x2[i] = keep + __shfl_xor_sync(0xffffffffu, send, 8);
        }
        float y;
        {
            const float send = s2v ? x2[0] : x2[1];
            const float keep = s2v ? x2[1] : x2[0];
            y = keep + __shfl_xor_sync(0xffffffffu, send, 4);
        }
        y += __shfl_xor_sync(0xffffffffu, y, 2);
        y += __shfl_xor_sync(0xffffffffu, y, 1);

        if (swr) {
            float* dst = yraw + (size_t)row * DINNER + h*PDIM + pbase + sidx;
            *dst = fmaf(Pt, y, *dst);
        }
    }
}

// ---------------- gate + gnorm fused with fp16x2 split (register-resident) --------
__global__ void gate_gnorm_split_k(const float* __restrict__ proj,
                                   const float* __restrict__ yraw,
                                   const float* __restrict__ gw,
                                   __half* __restrict__ out, size_t S)
{
    __shared__ float red[32];
    const int r = blockIdx.x;
    const int tid = threadIdx.x;
    const float* pz = proj + (size_t)r * PROJ_DIM;
    const float* yr = yraw + (size_t)r * DINNER;

    float g[2][4];
    float s = 0.f;
    #pragma unroll
    for (int it = 0; it < 2; it++) {
        const int d = (tid + it*256) * 4;
        const float4 zv = *(const float4*)(pz + d);
        const float4 yv = *(const float4*)(yr + d);
        g[it][0] = yv.x * zv.x / (1.f + expf(-zv.x));
        g[it][1] = yv.y * zv.y / (1.f + expf(-zv.y));
        g[it][2] = yv.z * zv.z / (1.f + expf(-zv.z));
        g[it][3] = yv.w * zv.w / (1.f + expf(-zv.w));
        s += g[it][0]*g[it][0] + g[it][1]*g[it][1] + g[it][2]*g[it][2] + g[it][3]*g[it][3];
    }
    const float tot = block_reduce_sum_256(s, red);
    const float rms = rsqrtf(tot / (float)DINNER + 1e-5f);

    __half2* p0 = (__half2*)(out + (size_t)r * DINNER);
    __half2* p1 = (__half2*)(out + S + (size_t)r * DINNER);
    #pragma unroll
    for (int it = 0; it < 2; it++) {
        const int d = (tid + it*256) * 4;
        const float4 wv = *(const float4*)(gw + d);
        float v0 = g[it][0]*rms*wv.x, v1 = g[it][1]*rms*wv.y;
        float v2 = g[it][2]*rms*wv.z, v3 = g[it][3]*rms*wv.w;
        __half h0a, h1a, h0b, h1b, h0c, h1c, h0d, h1d;
        split2(v0, h0a, h1a); split2(v1, h0b, h1b);
        split2(v2, h0c, h1c); split2(v3, h0d, h1d);
        p0[d/2]   = __halves2half2(h0a, h0b);
        p0[d/2+1] = __halves2half2(h0c, h0d);
        p1[d/2]   = __halves2half2(h1a, h1b);
        p1[d/2+1] = __halves2half2(h1c, h1d);
    }
}

// ---------------- mean over T per batch ----------------
__global__ void pool_k(const float* __restrict__ xin, float* __restrict__ pooled)
{
    const int b = blockIdx.x;
    const int d = blockIdx.y * 256 + threadIdx.x;
    float s = 0.f;
    for (int t = 0; t < TSEQ; t++)
        s += xin[(size_t)(b*TSEQ + t) * DMODEL + d];
    pooled[b*DMODEL + d] = s * (1.f / (float)TSEQ);
}

// ---------------- head GEMM + bias + L2-normalize ----------------
__global__ void head_k(const float* __restrict__ pooled,
                       const float* __restrict__ hw,
                       const float* __restrict__ hb,
                       float* __restrict__ out)
{
    __shared__ float sp[DMODEL];
    __shared__ float so[EDIM];
    __shared__ float red[32];
    const int b = blockIdx.x;

    for (int d = threadIdx.x; d < DMODEL; d += 256) sp[d] = pooled[b*DMODEL + d];
    __syncthreads();

    float acc[EDIM/256];
    #pragma unroll
    for (int m = 0; m < EDIM/256; m++) acc[m] = hb[threadIdx.x + m*256];
    for (int k = 0; k < DMODEL; k++) {
        const float p = sp[k];
        #pragma unroll
        for (int m = 0; m < EDIM/256; m++)
            acc[m] = fmaf(p, hw[(size_t)k*EDIM + threadIdx.x + m*256], acc[m]);
    }
    #pragma unroll
    for (int m = 0; m < EDIM/256; m++) so[threadIdx.x + m*256] = acc[m];
    __syncthreads();

    float s = 0.f;
    for (int e = threadIdx.x; e < EDIM; e += 256) s = fmaf(so[e], so[e], s);
    const float tot = block_reduce_sum_256(s, red);
    const float inv = 1.f / fmaxf(sqrtf(tot), 1e-12f);
    for (int e = threadIdx.x; e < EDIM; e += 256)
        out[(size_t)b*EDIM + e] = so[e] * inv;
}

// ---------------- host launcher ----------------
extern "C" void kernel_launch(void* const* d_in, const int* in_sizes, int n_in,
                              void* d_out, int out_size)
{
    const float* visual   = (const float*)d_in[0];
    const float* query    = (const float*)d_in[1];
    const float* vis_w    = (const float*)d_in[2];
    const float* vis_b    = (const float*)d_in[3];
    const float* qry_w    = (const float*)d_in[4];
    const float* qry_b    = (const float*)d_in[5];
    const float* norm_ws  = (const float*)d_in[6];
    const float* in_ws    = (const float*)d_in[7];
    const float* dt_bias  = (const float*)d_in[8];
    const float* A_logs   = (const float*)d_in[9];
    const float* D_ssm    = (const float*)d_in[10];
    const float* gnorm_ws = (const float*)d_in[11];
    const float* out_ws   = (const float*)d_in[12];
    const float* norm_f_w = (const float*)d_in[13];
    const float* head_w   = (const float*)d_in[14];
    const float* head_b   = (const float*)d_in[15];
    float* out = (float*)d_out;

    float *hidden, *xin, *proj, *yraw, *pooled, *vstate, *cumP;
    __half *ah, *bw;
    cudaGetSymbolAddress((void**)&hidden, g_hidden);
    cudaGetSymbolAddress((void**)&xin,    g_xin);
    cudaGetSymbolAddress((void**)&proj,   g_proj);
    cudaGetSymbolAddress((void**)&yraw,   g_yraw);
    cudaGetSymbolAddress((void**)&pooled, g_pooled);
    cudaGetSymbolAddress((void**)&vstate, g_vstate);
    cudaGetSymbolAddress((void**)&cumP,   g_cumP);
    cudaGetSymbolAddress((void**)&ah,     g_ah);
    cudaGetSymbolAddress((void**)&bw,     g_bw);

    cudaFuncSetAttribute(hgemm_t<4>, cudaFuncAttributeMaxDynamicSharedMemorySize, GSMEM4);
    cudaFuncSetAttribute(hgemm_t<2>, cudaFuncAttributeMaxDynamicSharedMemorySize, GSMEM2);

    const dim3 blk(256);

    cudaStream_t s2;
    cudaStreamCreateWithFlags(&s2, cudaStreamNonBlocking);
    cudaEvent_t evFork, evS[NLAYERS], evP[NLAYERS];
    cudaEventCreateWithFlags(&evFork, cudaEventDisableTiming);
    for (int i = 0; i < NLAYERS; i++) {
        cudaEventCreateWithFlags(&evS[i], cudaEventDisableTiming);
        cudaEventCreateWithFlags(&evP[i], cudaEventDisableTiming);
    }

    auto slice = [&](int i) -> __half* { return bw + W_L_OFF + (size_t)(i & 1) * W_L_SZ; };

    cudaEventRecord(evFork, 0);
    cudaStreamWaitEvent(s2, evFork, 0);
    tsplit2f<<<dim3(PROJ_DIM/32, DMODEL/64), blk, 0, s2>>>(in_ws, slice(0), DMODEL, PROJ_DIM);
    tsplit2f<<<dim3(DMODEL/32, DINNER/64), blk, 0, s2>>>(out_ws, slice(0) + 2*W_IN_PL, DINNER, DMODEL);
    cudaEventRecord(evP[0], s2);

    // ---- initial projections into hidden[b, t, :] ----
    {
        const size_t S = (size_t)BATCH*TVIS*DMODEL;
        split2_x<<<(unsigned)((S + 255)/256), blk>>>(visual, ah, S);
        tsplit2f<<<dim3(DMODEL/32, DMODEL/64), blk>>>(vis_w, bw + W_VIS_OFF, DMODEL, DMODEL);
        hgemm_t<2><<<dim3(DMODEL/64, (BATCH*TVIS)/64), blk, GSMEM2>>>(
            ah, S, bw + W_VIS_OFF, W_VIS_PL, hidden,
            BATCH*TVIS, DMODEL, DMODEL, vis_b, 0, TVIS, TSEQ, 0);
    }
    {
        const size_t S = (size_t)BATCH*TQRY*DMODEL;
        split2_x<<<(unsigned)((S + 255)/256), blk>>>(query, ah, S);
        tsplit2f<<<dim3(DMODEL/32, DMODEL/64), blk>>>(qry_w, bw + W_QRY_OFF, DMODEL, DMODEL);
        hgemm_t<2><<<dim3(DMODEL/64, (BATCH*TQRY)/64), blk, GSMEM2>>>(
            ah, S, bw + W_QRY_OFF, W_VIS_PL, hidden,
            BATCH*TQRY, DMODEL, DMODEL, qry_b, 0, TQRY, TSEQ, TVIS);
    }

    for (int i = 0; i < NLAYERS; i++) {
        const size_t SA = (size_t)ROWS*DMODEL;
        rmsnorm_split_k<<<ROWS, blk>>>(hidden, norm_ws + (size_t)i*DMODEL, ah, SA);

        cudaStreamWaitEvent(0, evP[i], 0);
        hgemm_t<4><<<dim3((PROJ_DIM + 127)/128, ROWS/64), blk, GSMEM4>>>(
            ah, SA, slice(i), W_IN_PL, proj,
            ROWS, PROJ_DIM, DMODEL, nullptr, 0, ROWS, ROWS, 0);

        // 2-chunk scan (dt/da computed in-CTA)
        scan_p1<<<dim3(NBH, 2), blk>>>(
            proj, dt_bias + (size_t)i*NHEADS, A_logs + (size_t)i*NHEADS,
            D_ssm + (size_t)i*NHEADS, yraw, vstate, cumP);
        cudaEventRecord(evS[i], 0);

        if (i + 1 < NLAYERS) {
            cudaStreamWaitEvent(s2, evS[i], 0);
            tsplit2f<<<dim3(PROJ_DIM/32, DMODEL/64), blk, 0, s2>>>(
                in_ws + (size_t)(i+1)*DMODEL*PROJ_DIM, slice(i+1), DMODEL, PROJ_DIM);
            tsplit2f<<<dim3(DMODEL/32, DINNER/64), blk, 0, s2>>>(
                out_ws + (size_t)(i+1)*DINNER*DMODEL, slice(i+1) + 2*W_IN_PL, DINNER, DMODEL);
            cudaEventRecord(evP[i+1], s2);
        }

        scan_p3<<<dim3(NBH, CHUNK/P3TS), blk>>>(proj, vstate, cumP, yraw);

        const size_t SG = (size_t)ROWS*DINNER;
        gate_gnorm_split_k<<<ROWS, blk>>>(proj, yraw, gnorm_ws + (size_t)i*DINNER, ah, SG);

        hgemm_t<2><<<dim3(DMODEL/64, ROWS/64), blk, GSMEM2>>>(
            ah, SG, slice(i) + 2*W_IN_PL, W_OUT_PL, hidden,
            ROWS, DMODEL, DINNER, nullptr, 1, ROWS, ROWS, 0);
    }

    rmsnorm_k<<<ROWS, blk>>>(hidden, norm_f_w, xin, DMODEL);
    pool_k<<<dim3(BATCH, DMODEL/256), blk>>>(xin, pooled);
    head_k<<<BATCH, blk>>>(pooled, head_w, head_b, out);
}

// round 17
// speedup vs baseline: 1.2024x; 1.0467x over previous
#include <cuda_runtime.h>
#include <cuda_fp16.h>
#include <math.h>
#include <stdint.h>

// ---------------- problem constants ----------------
#define BATCH   4
#define TSEQ    288
#define TVIS    256
#define TQRY    32
#define DMODEL  1024
#define DINNER  2048
#define NHEADS  32
#define NSTATE  128
#define PDIM    64
#define NLAYERS 12
#define PROJ_DIM 4384
#define EDIM    1536
#define ROWS    (BATCH*TSEQ)    // 1152
#define ALPHA_C 0.5f
#define NBH     (BATCH*NHEADS)  // 128
#define CHUNK   144             // 2 chunks of 144
#define P3TS    16              // 144 = 9*16
#define PNSZ    (PDIM*NSTATE)

// weight-slice geometry (halves)
#define W_VIS_OFF   0ull
#define W_VIS_PL    (1024ull*1024ull)
#define W_QRY_OFF   (2ull*W_VIS_PL)
#define W_L_OFF     (4ull*W_VIS_PL)
#define W_IN_PL     ((size_t)DMODEL*PROJ_DIM)
#define W_OUT_PL    ((size_t)DINNER*DMODEL)
#define W_L_SZ      (2ull*W_IN_PL + 2ull*W_OUT_PL)
#define W_TOTAL     (W_L_OFF + 2ull*W_L_SZ)

// ---------------- scratch (device globals; no allocation) ----------------
__device__ float g_hidden[ROWS*DMODEL];
__device__ float g_xin   [ROWS*DMODEL];
__device__ float g_proj  [ROWS*PROJ_DIM];
__device__ float g_yraw  [ROWS*DINNER];
__device__ float g_pooled[BATCH*DMODEL];
__device__ float g_vstate[(size_t)NBH*PNSZ];
__device__ float g_cumP  [NBH*TSEQ];
__device__ __align__(16) __half g_ah[2ull*1152*2048];
__device__ __align__(16) __half g_bw[W_TOTAL];

// ---------------- helpers ----------------
__device__ __forceinline__ float block_reduce_sum_256(float v, float* red)
{
    #pragma unroll
    for (int o = 16; o; o >>= 1) v += __shfl_xor_sync(0xffffffffu, v, o);
    const int warp = threadIdx.x >> 5, lane = threadIdx.x & 31;
    if (lane == 0) red[warp] = v;
    __syncthreads();
    if (threadIdx.x < 32) {
        float t = (threadIdx.x < 8) ? red[threadIdx.x] : 0.f;
        #pragma unroll
        for (int o = 4; o; o >>= 1) t += __shfl_xor_sync(0xffffffffu, t, o);
        if (threadIdx.x == 0) red[0] = t;
    }
    __syncthreads();
    return red[0];
}

__device__ __forceinline__ void split2(float x, __half& h0, __half& h1)
{
    h0 = __float2half_rn(x);
    h1 = __float2half_rn(x - __half2float(h0));
}

#define MMA16(cc, aa, bb)                                                        \
  asm volatile("mma.sync.aligned.m16n8k16.row.col.f32.f16.f16.f32 "             \
    "{%0,%1,%2,%3}, {%4,%5,%6,%7}, {%8,%9}, {%0,%1,%2,%3};\n"                    \
    : "+f"((cc)[0]), "+f"((cc)[1]), "+f"((cc)[2]), "+f"((cc)[3])                 \
    : "r"((aa)[0]), "r"((aa)[1]), "r"((aa)[2]), "r"((aa)[3]),                    \
      "r"((bb)[0]), "r"((bb)[1]))

__device__ __forceinline__ void ldsm4(uint32_t* r, uint32_t addr)
{
    asm volatile("ldmatrix.sync.aligned.m8n8.x4.shared.b16 {%0,%1,%2,%3}, [%4];"
                 : "=r"(r[0]), "=r"(r[1]), "=r"(r[2]), "=r"(r[3]) : "r"(addr));
}
__device__ __forceinline__ void ldsm2(uint32_t* r, uint32_t addr)
{
    asm volatile("ldmatrix.sync.aligned.m8n8.x2.shared.b16 {%0,%1}, [%2];"
                 : "=r"(r[0]), "=r"(r[1]) : "r"(addr));
}

__device__ __forceinline__ void cpasync16(uint32_t dst, const void* src, int sz)
{
    asm volatile("cp.async.cg.shared.global [%0], [%1], 16, %2;\n"
                 :: "r"(dst), "l"(src), "r"(sz));
}

// ---------------- prep: split fp32 -> 2 fp16 planes ----------------
__global__ void split2_x(const float* __restrict__ x, __half* __restrict__ out, size_t S)
{
    size_t i = (size_t)blockIdx.x * blockDim.x + threadIdx.x;
    if (i < S) {
        __half h0, h1; split2(x[i], h0, h1);
        out[i] = h0; out[S + i] = h1;
    }
}

// ---------------- prep: transpose KxN fp32 -> 2 planes [N][K] fp16 ----------------
__global__ void tsplit2f(const float* __restrict__ W, __half* __restrict__ out,
                         int K, int N)
{
    __shared__ float tile[64][33];
    const int n0 = blockIdx.x * 32, k0 = blockIdx.y * 64;
    const int tid = threadIdx.x;
    const int r = tid >> 5, c = tid & 31;
    #pragma unroll
    for (int i = 0; i < 8; i++)
        tile[i*8 + r][c] = W[(size_t)(k0 + i*8 + r) * N + n0 + c];
    __syncthreads();

    const size_t NK = (size_t)N * K;
    const int ns = tid >> 5;
    const int kp = tid & 31;
    #pragma unroll
    for (int j = 0; j < 4; j++) {
        const int nl = j*8 + ns;
        const int n  = n0 + nl;
        const float f0 = tile[2*kp    ][nl];
        const float f1 = tile[2*kp + 1][nl];
        __half a0, a1, b0, b1;
        split2(f0, a0, a1);
        split2(f1, b0, b1);
        __half2* p0 = (__half2*)(out + (size_t)n * K + k0);
        __half2* p1 = (__half2*)(out + NK + (size_t)n * K + k0);
        p0[kp] = __halves2half2(a0, b0);
        p1[kp] = __halves2half2(a1, b1);
    }
}

// ---------------- fp16x2 mma.sync GEMM, BM=64, BN=32*NI, 2 CTAs/SM ----------------
#define APLANE 8192
template<int NI>
__global__ __launch_bounds__(256, 2)
void hgemm_t(const __half* __restrict__ Ah, size_t aplane,
             const __half* __restrict__ Bh, size_t bplane,
             float* __restrict__ C, int M, int N, int K,
             const float* __restrict__ bias, int accum,
             int Tin, int Tout, int toff)
{
    constexpr int BN      = 32 * NI;
    constexpr int BPLANEx = BN * 128;
    constexpr int STAGE   = 2*APLANE + 2*BPLANEx;
    constexpr int TPB     = 256 / BN;

    extern __shared__ char sm[];
    const uint32_t smb = (uint32_t)__cvta_generic_to_shared(sm);

    const int tid  = threadIdx.x;
    const int warp = tid >> 5, lane = tid & 31;
    const int gid  = lane >> 2, tg = lane & 3;
    const int row0 = blockIdx.y * 64;
    const int col0 = blockIdx.x * BN;
    const int m_off = (warp & 1) * 32;
    const int n_off = (warp >> 1) * (8 * NI);

    float c[2][NI][4];
    #pragma unroll
    for (int mi = 0; mi < 2; mi++)
        #pragma unroll
        for (int ni = 0; ni < NI; ni++)
            #pragma unroll
            for (int q = 0; q < 4; q++) c[mi][ni][q] = 0.f;

    const int larow  = tid >> 2;
    const int cbase  = (tid & 3) * 2;
    const int lbrow  = tid / TPB;
    const int cbaseB = (tid % TPB) * NI;
    const int brow   = col0 + lbrow;
    const int bval   = (brow < N) ? 16 : 0;
    const __half* Asrc0 = Ah + (size_t)(row0 + larow) * K;
    const __half* Asrc1 = Asrc0 + aplane;
    const __half* Bsrc0 = Bh + (size_t)((brow < N) ? brow : 0) * K;
    const __half* Bsrc1 = Bsrc0 + bplane;

    const int la   = lane & 15;
    const int asel = lane >> 4;
    const int lb   = lane & 7;
    const int bsel = (lane >> 3) & 1;
    uint32_t aoff[2]; int ar7[2];
    #pragma unroll
    for (int mi = 0; mi < 2; mi++) {
        const int r = m_off + mi*16 + la;
        aoff[mi] = (uint32_t)r * 128;
        ar7[mi]  = r & 7;
    }
    uint32_t boff[NI]; int br7[NI];
    #pragma unroll
    for (int ni = 0; ni < NI; ni++) {
        const int r = n_off + ni*8 + lb;
        boff[ni] = (uint32_t)r * 128;
        br7[ni]  = r & 7;
    }

    const int nc = K >> 6;

    {
        const uint32_t sb = smb;
        #pragma unroll
        for (int j = 0; j < 2; j++) {
            const int ch = cbase + j;
            const uint32_t sw = (uint32_t)((ch ^ (larow & 7)) << 4);
            cpasync16(sb + larow*128 + sw,          Asrc0 + ch*8, 16);
            cpasync16(sb + APLANE + larow*128 + sw, Asrc1 + ch*8, 16);
        }
        #pragma unroll
        for (int j = 0; j < NI; j++) {
            const int ch = cbaseB + j;
            const uint32_t sw = (uint32_t)((ch ^ (lbrow & 7)) << 4);
            cpasync16(sb + 2*APLANE + lbrow*128 + sw,           Bsrc0 + ch*8, bval);
            cpasync16(sb + 2*APLANE + BPLANEx + lbrow*128 + sw, Bsrc1 + ch*8, bval);
        }
        asm volatile("cp.async.commit_group;\n");
    }

    for (int kc = 0; kc < nc; kc++) {
        if (kc + 1 < nc) {
            const int k0 = (kc + 1) << 6;
            const uint32_t sb = smb + ((kc + 1) & 1) * STAGE;
            #pragma unroll
            for (int j = 0; j < 2; j++) {
                const int ch = cbase + j;
                const uint32_t sw = (uint32_t)((ch ^ (larow & 7)) << 4);
                cpasync16(sb + larow*128 + sw,          Asrc0 + k0 + ch*8, 16);
                cpasync16(sb + APLANE + larow*128 + sw, Asrc1 + k0 + ch*8, 16);
            }
            #pragma unroll
            for (int j = 0; j < NI; j++) {
                const int ch = cbaseB + j;
                const uint32_t sw = (uint32_t)((ch ^ (lbrow & 7)) << 4);
                cpasync16(sb + 2*APLANE + lbrow*128 + sw,           Bsrc0 + k0 + ch*8, bval);
                cpasync16(sb + 2*APLANE + BPLANEx + lbrow*128 + sw, Bsrc1 + k0 + ch*8, bval);
            }
        }
        asm volatile("cp.async.commit_group;\n");
        asm volatile("cp.async.wait_group 1;\n");
        __syncthreads();

        const uint32_t S0 = smb + (kc & 1) * STAGE;
        const uint32_t S1 = S0 + APLANE;
        const uint32_t S2 = S0 + 2*APLANE;
        const uint32_t S3 = S2 + BPLANEx;

        #pragma unroll
        for (int s = 0; s < 4; s++) {
            uint32_t b0[NI][2], b1[NI][2];
            #pragma unroll
            for (int ni = 0; ni < NI; ni++) {
                const uint32_t swb = (uint32_t)(((2*s + bsel) ^ br7[ni]) << 4);
                ldsm2(b0[ni], S2 + boff[ni] + swb);
                ldsm2(b1[ni], S3 + boff[ni] + swb);
            }
            #pragma unroll
            for (int mi = 0; mi < 2; mi++) {
                const uint32_t swa = (uint32_t)(((2*s + asel) ^ ar7[mi]) << 4);
                uint32_t a0[4], a1[4];
                ldsm4(a0, S0 + aoff[mi] + swa);
                ldsm4(a1, S1 + aoff[mi] + swa);
                #pragma unroll
                for (int ni = 0; ni < NI; ni++) {
                    MMA16(c[mi][ni], a0, b0[ni]);
                    MMA16(c[mi][ni], a0, b1[ni]);
                    MMA16(c[mi][ni], a1, b0[ni]);
                }
            }
        }
        __syncthreads();
    }

    #pragma unroll
    for (int mi = 0; mi < 2; mi++) {
        #pragma unroll
        for (int half = 0; half < 2; half++) {
            const int r = row0 + m_off + mi*16 + gid + half*8;
            const int orow = (r / Tin) * Tout + toff + (r % Tin);
            #pragma unroll
            for (int ni = 0; ni < NI; ni++) {
                const int col = col0 + n_off + ni*8 + tg*2;
                if (col < N) {
                    float v0 = c[mi][ni][half*2 + 0];
                    float v1 = c[mi][ni][half*2 + 1];
                    if (bias) { v0 += bias[col]; v1 += bias[col+1]; }
                    float* dst = C + (size_t)orow * N + col;
                    if (accum) { v0 += dst[0]; v1 += dst[1]; }
                    *reinterpret_cast<float2*>(dst) = make_float2(v0, v1);
                }
            }
        }
    }
}

#define GSMEM2 (2*(2*APLANE + 2*64*128))

// ---------------- RMSNorm (fp32 out, final layer) ----------------
__global__ void rmsnorm_k(const float* __restrict__ x, const float* __restrict__ w,
                          float* __restrict__ out, int D)
{
    __shared__ float red[32];
    const int r = blockIdx.x;
    const float* xr = x + (size_t)r * D;
    float s = 0.f;
    for (int d = threadIdx.x; d < D; d += 256) { float v = xr[d]; s = fmaf(v, v, s); }
    const float tot = block_reduce_sum_256(s, red);
    const float rms = rsqrtf(tot / (float)D + 1e-5f);
    for (int d = threadIdx.x; d < D; d += 256)
        out[(size_t)r * D + d] = xr[d] * rms * w[d];
}

// ---------------- RMSNorm fused with fp16x2 split (D = 1024) ----------------
__global__ void rmsnorm_split_k(const float* __restrict__ x, const float* __restrict__ w,
                                __half* __restrict__ out, size_t S)
{
    __shared__ float red[32];
    const int r = blockIdx.x;
    const int tid = threadIdx.x;
    const float4 xv = *(const float4*)(x + (size_t)r * DMODEL + tid*4);
    const float4 wv = *(const float4*)(w + tid*4);
    float s = xv.x*xv.x + xv.y*xv.y + xv.z*xv.z + xv.w*xv.w;
    const float tot = block_reduce_sum_256(s, red);
    const float rms = rsqrtf(tot / (float)DMODEL + 1e-5f);
    float v0 = xv.x*rms*wv.x, v1 = xv.y*rms*wv.y, v2 = xv.z*rms*wv.z, v3 = xv.w*rms*wv.w;
    __half h0a, h1a, h0b, h1b, h0c, h1c, h0d, h1d;
    split2(v0, h0a, h1a); split2(v1, h0b, h1b);
    split2(v2, h0c, h1c); split2(v3, h0d, h1d);
    __half2* p0 = (__half2*)(out + (size_t)r * DMODEL);
    __half2* p1 = (__half2*)(out + S + (size_t)r * DMODEL);
    p0[tid*2]   = __halves2half2(h0a, h0b);
    p0[tid*2+1] = __halves2half2(h0c, h0d);
    p1[tid*2]   = __halves2half2(h1a, h1b);
    p1[tid*2+1] = __halves2half2(h1c, h1d);
}

// ---------------- scan phase 1: two half-sequence local scans ----------------
#define SCX  0
#define SCB  64
#define SCC  192
__global__ void scan_p1(const float* __restrict__ proj,
                        const float* __restrict__ dt_bias,
                        const float* __restrict__ A_log,
                        const float* __restrict__ Dssm,
                        float* __restrict__ yraw,
                        float* __restrict__ vstate,
                        float* __restrict__ cumP)
{
    const int bh   = blockIdx.x;
    const int ch   = blockIdx.y;            // 0 or 1
    const int b    = bh >> 5;
    const int h    = bh & 31;
    const int t0   = ch * CHUNK;
    const int t1   = t0 + CHUNK;
    const int tid  = threadIdx.x;
    const int warp = tid >> 5, lane = tid & 31;

    __shared__ float st[3][324];
    __shared__ float sdt[CHUNK];
    __shared__ float sda[CHUNK];
    __shared__ float sdtprev;

    const float dtb  = dt_bias[h];
    const float Aval = -expf(A_log[h]);
    const float Dval = Dssm[h];

    if (tid < CHUNK) {
        const float vdt = proj[(size_t)(b*TSEQ + t0 + tid)*PROJ_DIM + 2*DINNER + 2*NSTATE + h] + dtb;
        const float dt = (vdt > 20.f) ? vdt : log1pf(expf(vdt));
        sdt[tid] = dt;
        sda[tid] = expf(dt * Aval);
    }
    if (tid == 255) {
        float v = 0.f;
        if (ch > 0) {
            const float vdt = proj[(size_t)(b*TSEQ + t0 - 1)*PROJ_DIM + 2*DINNER + 2*NSTATE + h] + dtb;
            v = (vdt > 20.f) ? vdt : log1pf(expf(vdt));
        }
        sdtprev = v;
    }

    float hs[8][4];
    #pragma unroll
    for (int i = 0; i < 8; i++)
        #pragma unroll
        for (int j = 0; j < 4; j++) hs[i][j] = 0.f;

    const int pbase = warp * 8;
    const int nbase = lane * 4;
    const bool s4 = (lane & 16) != 0;
    const bool s3 = (lane & 8)  != 0;
    const bool s2v = (lane & 4) != 0;
    const int  sidx = (lane >> 2) & 7;
    const bool swr  = ((lane & 3) == 0);

    float xprev[8], bprev[4];
    #pragma unroll
    for (int i = 0; i < 8; i++) xprev[i] = 0.f;
    #pragma unroll
    for (int j = 0; j < 4; j++) bprev[j] = 0.f;
    if (ch > 0) {
        const float* pp = proj + (size_t)(b * TSEQ + t0 - 1) * PROJ_DIM;
        #pragma unroll
        for (int i = 0; i < 8; i++) xprev[i] = pp[DINNER + h*PDIM + pbase + i];
        #pragma unroll
        for (int j = 0; j < 4; j++) bprev[j] = pp[2*DINNER + nbase + j];
    }

    uint32_t stb[3];
    stb[0] = (uint32_t)__cvta_generic_to_shared(&st[0][0]);
    stb[1] = (uint32_t)__cvta_generic_to_shared(&st[1][0]);
    stb[2] = (uint32_t)__cvta_generic_to_shared(&st[2][0]);

    auto issue = [&](int buf, int t) {
        const float* pr = proj + (size_t)(b * TSEQ + t) * PROJ_DIM;
        const uint32_t base = stb[buf];
        if (tid < 16)
            cpasync16(base + (SCX + tid*4)*4,  pr + DINNER + h*PDIM + tid*4, 16);
        else if (tid < 48)
            cpasync16(base + (SCB + (tid-16)*4)*4, pr + 2*DINNER + (tid-16)*4, 16);
        else if (tid < 80)
            cpasync16(base + (SCC + (tid-48)*4)*4, pr + 2*DINNER + NSTATE + (tid-48)*4, 16);
        asm volatile("cp.async.commit_group;\n");
    };

    issue(0, t0);
    issue(1, t0 + 1);

    __syncthreads();
    float dtprev = sdtprev;

    float cum = 1.f;
    int buf = 0;
    for (int t = t0; t < t1; t++) {
        asm volatile("cp.async.wait_group 1;\n");
        __syncthreads();
        if (t + 2 < t1) {
            int nb = buf + 2; if (nb >= 3) nb -= 3;
            issue(nb, t + 2);
        } else {
            asm volatile("cp.async.commit_group;\n");
        }

        const float* sb = st[buf];
        const float dt  = sdt[t - t0];
        const float da  = sda[t - t0];
        const float cu  = (1.f - ALPHA_C) * dt;
        const float cup = da * ALPHA_C * dtprev;
        if (ch == 1) {
            cum *= da;
            if (tid == 0) cumP[bh * TSEQ + t] = cum;
        }

        float bc[4], cc[4];
        #pragma unroll
        for (int j = 0; j < 4; j++) { bc[j] = sb[SCB + nbase + j]; cc[j] = sb[SCC + nbase + j]; }

        const int row = b * TSEQ + t;

        float v[8];
        #pragma unroll
        for (int i = 0; i < 8; i++) {
            const float xr  = sb[SCX + pbase + i];
            const float xpi = cup * xprev[i];
            const float xci = cu  * xr;
            float yp = 0.f;
            #pragma unroll
            for (int j = 0; j < 4; j++) {
                const float u = fmaf(xpi, bprev[j], xci * bc[j]);
                hs[i][j] = fmaf(da, hs[i][j], u);
                yp = fmaf(hs[i][j], cc[j], yp);
            }
            v[i] = yp;
            xprev[i] = xr;
        }

        float w4[4];
        #pragma unroll
        for (int i = 0; i < 4; i++) {
            const float send = s4 ? v[i]   : v[i+4];
            const float keep = s4 ? v[i+4] : v[i];
            w4[i] = keep + __shfl_xor_sync(0xffffffffu, send, 16);
        }
        float x2[2];
        #pragma unroll
        for (int i = 0; i < 2; i++) {
            const float send = s3 ? w4[i]   : w4[i+2];
            const float keep = s3 ? w4[i+2] : w4[i];
            x2[i] = keep + __shfl_xor_sync(0xffffffffu, send, 8);
        }
        float y;
        {
            const float send = s2v ? x2[0] : x2[1];
            const float keep = s2v ? x2[1] : x2[0];
            y = keep + __shfl_xor_sync(0xffffffffu, send, 4);
        }
        y += __shfl_xor_sync(0xffffffffu, y, 2);
        y += __shfl_xor_sync(0xffffffffu, y, 1);

        if (swr)
            yraw[(size_t)row * DINNER + h*PDIM + pbase + sidx] =
                fmaf(Dval, sb[SCX + pbase + sidx], y);

        #pragma unroll
        for (int j = 0; j < 4; j++) bprev[j] = bc[j];
        dtprev = dt;
        buf++; if (buf >= 3) buf = 0;
    }

    if (ch == 0) {
        float* V = vstate + (size_t)bh * PNSZ;
        #pragma unroll
        for (int i = 0; i < 8; i++)
            #pragma unroll
            for (int j = 0; j < 4; j++)
                V[(pbase + i) * NSTATE + nbase + j] = hs[i][j];
    }
}

// ---------------- scan phase 3: y_t += P_t * (C_t . V0), second half only --------
__global__ void scan_p3(const float* __restrict__ proj,
                        const float* __restrict__ vstate,
                        const float* __restrict__ cumP,
                        float* __restrict__ yraw)
{
    const int bh   = blockIdx.x;
    const int b    = bh >> 5;
    const int h    = bh & 31;
    const int tid  = threadIdx.x;
    const int warp = tid >> 5, lane = tid & 31;
    const int pbase = warp * 8;
    const int nbase = lane * 4;
    const bool s4 = (lane & 16) != 0;
    const bool s3 = (lane & 8)  != 0;
    const bool s2v = (lane & 4) != 0;
    const int  sidx = (lane >> 2) & 7;
    const bool swr  = ((lane & 3) == 0);

    const float* V = vstate + (size_t)bh * PNSZ;
    float hin[8][4];
    #pragma unroll
    for (int i = 0; i < 8; i++) {
        const float4 q = *(const float4*)(V + (pbase + i) * NSTATE + nbase);
        hin[i][0] = q.x; hin[i][1] = q.y; hin[i][2] = q.z; hin[i][3] = q.w;
    }

    const int t0 = CHUNK + blockIdx.y * P3TS;
    for (int t = t0; t < t0 + P3TS; t++) {
        const int row = b * TSEQ + t;
        const float* pr = proj + (size_t)row * PROJ_DIM;
        const float Pt = cumP[bh * TSEQ + t];

        const float4 cq = *(const float4*)(pr + 2*DINNER + NSTATE + nbase);
        float cc[4] = {cq.x, cq.y, cq.z, cq.w};

        float v[8];
        #pragma unroll
        for (int i = 0; i < 8; i++) {
            float yp = 0.f;
            #pragma unroll
            for (int j = 0; j < 4; j++) yp = fmaf(hin[i][j], cc[j], yp);
            v[i] = yp;
        }

        float w4[4];
        #pragma unroll
        for (int i = 0; i < 4; i++) {
            const float send = s4 ? v[i]   : v[i+4];
            const float keep = s4 ? v[i+4] : v[i];
            w4[i] = keep + __shfl_xor_sync(0xffffffffu, send, 16);
        }
        float x2[2];
        #pragma unroll
        for (int i = 0; i < 2; i++) {
            const float send = s3 ? w4[i]   : w4[i+2];
            const float keep = s3 ? w4[i+2] : w4[i];
            x2[i] = keep + __shfl_xor_sync(0xffffffffu, send, 8);
        }
        float y;
        {
            const float send = s2v ? x2[0] : x2[1];
            const float keep = s2v ? x2[1] : x2[0];
            y = keep + __shfl_xor_sync(0xffffffffu, send, 4);
        }
        y += __shfl_xor_sync(0xffffffffu, y, 2);
        y += __shfl_xor_sync(0xffffffffu, y, 1);

        if (swr) {
            float* dst = yraw + (size_t)row * DINNER + h*PDIM + pbase + sidx;
            *dst = fmaf(Pt, y, *dst);
        }
    }
}

// ---------------- gate + gnorm fused with fp16x2 split (register-resident) --------
__global__ void gate_gnorm_split_k(const float* __restrict__ proj,
                                   const float* __restrict__ yraw,
                                   const float* __restrict__ gw,
                                   __half* __restrict__ out, size_t S)
{
    __shared__ float red[32];
    const int r = blockIdx.x;
    const int tid = threadIdx.x;
    const float* pz = proj + (size_t)r * PROJ_DIM;
    const float* yr = yraw + (size_t)r * DINNER;

    float g[2][4];
    float s = 0.f;
    #pragma unroll
    for (int it = 0; it < 2; it++) {
        const int d = (tid + it*256) * 4;
        const float4 zv = *(const float4*)(pz + d);
        const float4 yv = *(const float4*)(yr + d);
        g[it][0] = yv.x * zv.x / (1.f + expf(-zv.x));
        g[it][1] = yv.y * zv.y / (1.f + expf(-zv.y));
        g[it][2] = yv.z * zv.z / (1.f + expf(-zv.z));
        g[it][3] = yv.w * zv.w / (1.f + expf(-zv.w));
        s += g[it][0]*g[it][0] + g[it][1]*g[it][1] + g[it][2]*g[it][2] + g[it][3]*g[it][3];
    }
    const float tot = block_reduce_sum_256(s, red);
    const float rms = rsqrtf(tot / (float)DINNER + 1e-5f);

    __half2* p0 = (__half2*)(out + (size_t)r * DINNER);
    __half2* p1 = (__half2*)(out + S + (size_t)r * DINNER);
    #pragma unroll
    for (int it = 0; it < 2; it++) {
        const int d = (tid + it*256) * 4;
        const float4 wv = *(const float4*)(gw + d);
        float v0 = g[it][0]*rms*wv.x, v1 = g[it][1]*rms*wv.y;
        float v2 = g[it][2]*rms*wv.z, v3 = g[it][3]*rms*wv.w;
        __half h0a, h1a, h0b, h1b, h0c, h1c, h0d, h1d;
        split2(v0, h0a, h1a); split2(v1, h0b, h1b);
        split2(v2, h0c, h1c); split2(v3, h0d, h1d);
        p0[d/2]   = __halves2half2(h0a, h0b);
        p0[d/2+1] = __halves2half2(h0c, h0d);
        p1[d/2]   = __halves2half2(h1a, h1b);
        p1[d/2+1] = __halves2half2(h1c, h1d);
    }
}

// ---------------- mean over T per batch ----------------
__global__ void pool_k(const float* __restrict__ xin, float* __restrict__ pooled)
{
    const int b = blockIdx.x;
    const int d = blockIdx.y * 256 + threadIdx.x;
    float s = 0.f;
    for (int t = 0; t < TSEQ; t++)
        s += xin[(size_t)(b*TSEQ + t) * DMODEL + d];
    pooled[b*DMODEL + d] = s * (1.f / (float)TSEQ);
}

// ---------------- head GEMM + bias + L2-normalize ----------------
__global__ void head_k(const float* __restrict__ pooled,
                       const float* __restrict__ hw,
                       const float* __restrict__ hb,
                       float* __restrict__ out)
{
    __shared__ float sp[DMODEL];
    __shared__ float so[EDIM];
    __shared__ float red[32];
    const int b = blockIdx.x;

    for (int d = threadIdx.x; d < DMODEL; d += 256) sp[d] = pooled[b*DMODEL + d];
    __syncthreads();

    float acc[EDIM/256];
    #pragma unroll
    for (int m = 0; m < EDIM/256; m++) acc[m] = hb[threadIdx.x + m*256];
    for (int k = 0; k < DMODEL; k++) {
        const float p = sp[k];
        #pragma unroll
        for (int m = 0; m < EDIM/256; m++)
            acc[m] = fmaf(p, hw[(size_t)k*EDIM + threadIdx.x + m*256], acc[m]);
    }
    #pragma unroll
    for (int m = 0; m < EDIM/256; m++) so[threadIdx.x + m*256] = acc[m];
    __syncthreads();

    float s = 0.f;
    for (int e = threadIdx.x; e < EDIM; e += 256) s = fmaf(so[e], so[e], s);
    const float tot = block_reduce_sum_256(s, red);
    const float inv = 1.f / fmaxf(sqrtf(tot), 1e-12f);
    for (int e = threadIdx.x; e < EDIM; e += 256)
        out[(size_t)b*EDIM + e] = so[e] * inv;
}

// ---------------- host launcher ----------------
extern "C" void kernel_launch(void* const* d_in, const int* in_sizes, int n_in,
                              void* d_out, int out_size)
{
    const float* visual   = (const float*)d_in[0];
    const float* query    = (const float*)d_in[1];
    const float* vis_w    = (const float*)d_in[2];
    const float* vis_b    = (const float*)d_in[3];
    const float* qry_w    = (const float*)d_in[4];
    const float* qry_b    = (const float*)d_in[5];
    const float* norm_ws  = (const float*)d_in[6];
    const float* in_ws    = (const float*)d_in[7];
    const float* dt_bias  = (const float*)d_in[8];
    const float* A_logs   = (const float*)d_in[9];
    const float* D_ssm    = (const float*)d_in[10];
    const float* gnorm_ws = (const float*)d_in[11];
    const float* out_ws   = (const float*)d_in[12];
    const float* norm_f_w = (const float*)d_in[13];
    const float* head_w   = (const float*)d_in[14];
    const float* head_b   = (const float*)d_in[15];
    float* out = (float*)d_out;

    float *hidden, *xin, *proj, *yraw, *pooled, *vstate, *cumP;
    __half *ah, *bw;
    cudaGetSymbolAddress((void**)&hidden, g_hidden);
    cudaGetSymbolAddress((void**)&xin,    g_xin);
    cudaGetSymbolAddress((void**)&proj,   g_proj);
    cudaGetSymbolAddress((void**)&yraw,   g_yraw);
    cudaGetSymbolAddress((void**)&pooled, g_pooled);
    cudaGetSymbolAddress((void**)&vstate, g_vstate);
    cudaGetSymbolAddress((void**)&cumP,   g_cumP);
    cudaGetSymbolAddress((void**)&ah,     g_ah);
    cudaGetSymbolAddress((void**)&bw,     g_bw);

    cudaFuncSetAttribute(hgemm_t<2>, cudaFuncAttributeMaxDynamicSharedMemorySize, GSMEM2);

    const dim3 blk(256);

    cudaStream_t s2;
    cudaStreamCreateWithFlags(&s2, cudaStreamNonBlocking);
    cudaEvent_t evFork, evS[NLAYERS], evP[NLAYERS];
    cudaEventCreateWithFlags(&evFork, cudaEventDisableTiming);
    for (int i = 0; i < NLAYERS; i++) {
        cudaEventCreateWithFlags(&evS[i], cudaEventDisableTiming);
        cudaEventCreateWithFlags(&evP[i], cudaEventDisableTiming);
    }

    auto slice = [&](int i) -> __half* { return bw + W_L_OFF + (size_t)(i & 1) * W_L_SZ; };

    cudaEventRecord(evFork, 0);
    cudaStreamWaitEvent(s2, evFork, 0);
    tsplit2f<<<dim3(PROJ_DIM/32, DMODEL/64), blk, 0, s2>>>(in_ws, slice(0), DMODEL, PROJ_DIM);
    tsplit2f<<<dim3(DMODEL/32, DINNER/64), blk, 0, s2>>>(out_ws, slice(0) + 2*W_IN_PL, DINNER, DMODEL);
    cudaEventRecord(evP[0], s2);

    // ---- initial projections into hidden[b, t, :] ----
    {
        const size_t S = (size_t)BATCH*TVIS*DMODEL;
        split2_x<<<(unsigned)((S + 255)/256), blk>>>(visual, ah, S);
        tsplit2f<<<dim3(DMODEL/32, DMODEL/64), blk>>>(vis_w, bw + W_VIS_OFF, DMODEL, DMODEL);
        hgemm_t<2><<<dim3(DMODEL/64, (BATCH*TVIS)/64), blk, GSMEM2>>>(
            ah, S, bw + W_VIS_OFF, W_VIS_PL, hidden,
            BATCH*TVIS, DMODEL, DMODEL, vis_b, 0, TVIS, TSEQ, 0);
    }
    {
        const size_t S = (size_t)BATCH*TQRY*DMODEL;
        split2_x<<<(unsigned)((S + 255)/256), blk>>>(query, ah, S);
        tsplit2f<<<dim3(DMODEL/32, DMODEL/64), blk>>>(qry_w, bw + W_QRY_OFF, DMODEL, DMODEL);
        hgemm_t<2><<<dim3(DMODEL/64, (BATCH*TQRY)/64), blk, GSMEM2>>>(
            ah, S, bw + W_QRY_OFF, W_VIS_PL, hidden,
            BATCH*TQRY, DMODEL, DMODEL, qry_b, 0, TQRY, TSEQ, TVIS);
    }

    for (int i = 0; i < NLAYERS; i++) {
        const size_t SA = (size_t)ROWS*DMODEL;
        rmsnorm_split_k<<<ROWS, blk>>>(hidden, norm_ws + (size_t)i*DMODEL, ah, SA);

        cudaStreamWaitEvent(0, evP[i], 0);
        // in-proj: NI=2 → grid 69x18 = 1242 CTAs (4.2 waves, smaller tail)
        hgemm_t<2><<<dim3((PROJ_DIM + 63)/64, ROWS/64), blk, GSMEM2>>>(
            ah, SA, slice(i), W_IN_PL, proj,
            ROWS, PROJ_DIM, DMODEL, nullptr, 0, ROWS, ROWS, 0);

        scan_p1<<<dim3(NBH, 2), blk>>>(
            proj, dt_bias + (size_t)i*NHEADS, A_logs + (size_t)i*NHEADS,
            D_ssm + (size_t)i*NHEADS, yraw, vstate, cumP);
        cudaEventRecord(evS[i], 0);

        if (i + 1 < NLAYERS) {
            cudaStreamWaitEvent(s2, evS[i], 0);
            tsplit2f<<<dim3(PROJ_DIM/32, DMODEL/64), blk, 0, s2>>>(
                in_ws + (size_t)(i+1)*DMODEL*PROJ_DIM, slice(i+1), DMODEL, PROJ_DIM);
            tsplit2f<<<dim3(DMODEL/32, DINNER/64), blk, 0, s2>>>(
                out_ws + (size_t)(i+1)*DINNER*DMODEL, slice(i+1) + 2*W_IN_PL, DINNER, DMODEL);
            cudaEventRecord(evP[i+1], s2);
        }

        scan_p3<<<dim3(NBH, CHUNK/P3TS), blk>>>(proj, vstate, cumP, yraw);

        const size_t SG = (size_t)ROWS*DINNER;
        gate_gnorm_split_k<<<ROWS, blk>>>(proj, yraw, gnorm_ws + (size_t)i*DINNER, ah, SG);

        hgemm_t<2><<<dim3(DMODEL/64, ROWS/64), blk, GSMEM2>>>(
            ah, SG, slice(i) + 2*W_IN_PL, W_OUT_PL, hidden,
            ROWS, DMODEL, DINNER, nullptr, 1, ROWS, ROWS, 0);
    }

    rmsnorm_k<<<ROWS, blk>>>(hidden, norm_f_w, xin, DMODEL);
    pool_k<<<dim3(BATCH, DMODEL/256), blk>>>(xin, pooled);
    head_k<<<BATCH, blk>>>(pooled, head_w, head_b, out);
}